// round 3
// baseline (speedup 1.0000x reference)
#include <cuda_runtime.h>
#include <math.h>

// Problem dims
#define BB 8
#define CI 64
#define CO 128
#define HH 256
#define WW 256

// Output offsets (ll, m_ll, lh, hl, hh, m_lh, m_hl, m_hh)
#define SUB (BB*CO*128*128)      // 16777216
#define MSK (BB*128*128)         // 131072
#define OFF_LL  0
#define OFF_MLL (SUB)
#define OFF_LH  (SUB + MSK)
#define OFF_HL  (2*SUB + MSK)
#define OFF_HH  (3*SUB + MSK)
#define OFF_MLH (4*SUB + MSK)
#define OFF_MHL (4*SUB + 2*MSK)
#define OFF_MHH (4*SUB + 3*MSK)

typedef unsigned long long ull;

// Scratch
__device__ float g_x[(size_t)BB*CO*HH*WW];     // conv out, then GDN in-place
__device__ float g_ratio[BB*HH*WW];            // >0 <=> valid
__device__ float g_inv_sigma;

__constant__ float c_h0[9] = {
    0.026748757410810f, -0.016864118442875f, -0.078223266528990f,
    0.266864118442875f,  0.602949018236360f,  0.266864118442875f,
   -0.078223266528990f, -0.016864118442875f,  0.026748757410810f};
__constant__ float c_h1[7] = {
    0.091271763114250f, -0.057543526228500f, -0.591271763114250f,
    1.115087052457000f, -0.591271763114250f, -0.057543526228500f,
    0.091271763114250f};

__device__ __forceinline__ int refl(int i, int n) {
    return i < 0 ? -i : (i >= n ? 2*n - 2 - i : i);
}

// f32x2 packed helpers (sm_100+)
__device__ __forceinline__ ull pk(float a, float b) {
    ull r; asm("mov.b64 %0, {%1, %2};" : "=l"(r) : "f"(a), "f"(b)); return r;
}
__device__ __forceinline__ void upk(ull v, float& a, float& b) {
    asm("mov.b64 {%0, %1}, %2;" : "=f"(a), "=f"(b) : "l"(v));
}
__device__ __forceinline__ ull fma2(ull a, ull b, ull c) {
    ull d; asm("fma.rn.f32x2 %0, %1, %2, %3;" : "=l"(d) : "l"(a), "l"(b), "l"(c));
    return d;
}
__device__ __forceinline__ ull mul2(ull a, ull b) {
    ull d; asm("mul.rn.f32x2 %0, %1, %2;" : "=l"(d) : "l"(a), "l"(b));
    return d;
}

// ---------------------------------------------------------------------------
// Spectral norm: one power-iteration step, writes 1/sigma
// ---------------------------------------------------------------------------
__global__ void spectral_kernel(const float* __restrict__ w,
                                const float* __restrict__ u)
{
    __shared__ float sv[576];
    __shared__ float red[256];
    int tid = threadIdx.x;
    float p = 0.f;
    for (int j = tid; j < 576; j += 256) {
        float s = 0.f;
        #pragma unroll 4
        for (int o = 0; o < 128; ++o) s += w[o*576 + j] * u[o];
        sv[j] = s;
        p += s * s;
    }
    red[tid] = p; __syncthreads();
    for (int s = 128; s > 0; s >>= 1) {
        if (tid < s) red[tid] += red[tid + s];
        __syncthreads();
    }
    float vinv = 1.f / (sqrtf(red[0]) + 1e-12f);
    __syncthreads();
    float q = 0.f;
    if (tid < 128) {
        float s = 0.f;
        #pragma unroll 4
        for (int j = 0; j < 576; ++j) s += w[tid*576 + j] * sv[j];
        s *= vinv;
        q = s * s;
    }
    red[tid] = q; __syncthreads();
    for (int s = 128; s > 0; s >>= 1) {
        if (tid < s) red[tid] += red[tid + s];
        __syncthreads();
    }
    if (tid == 0) g_inv_sigma = rsqrtf(red[0]);
}

// ---------------------------------------------------------------------------
// Partial-conv mask renormalization: ratio = valid ? 9/msum : 0
// ---------------------------------------------------------------------------
__global__ void ratio_kernel(const float* __restrict__ mask)
{
    int idx = blockIdx.x * 256 + threadIdx.x;
    if (idx >= BB*HH*WW) return;
    int b = idx >> 16, rem = idx & 65535;
    int h = rem >> 8, wq = rem & 255;
    float s = 0.f;
    #pragma unroll
    for (int dh = -1; dh <= 1; ++dh) {
        int gh = h + dh;
        if ((unsigned)gh >= (unsigned)HH) continue;
        #pragma unroll
        for (int dw = -1; dw <= 1; ++dw) {
            int gw = wq + dw;
            if ((unsigned)gw >= (unsigned)WW) continue;
            s += mask[(b*HH + gh)*WW + gw];
        }
    }
    g_ratio[idx] = s > 0.f ? 9.f / fmaxf(s, 1e-8f) : 0.f;
}

// ---------------------------------------------------------------------------
// Partial conv 3x3 (spectral-normalized), f32x2 packed (2 pixels / thread)
// Block: 32 oc x (8h x 64w) tile, 256 threads, 8-channel smem chunks
// ---------------------------------------------------------------------------
__global__ __launch_bounds__(256)
void conv_kernel(const float* __restrict__ x, const float* __restrict__ mask,
                 const float* __restrict__ weight, const float* __restrict__ bias)
{
    __shared__ float sIn[8][10][66];
    __shared__ ull   sW2[8][32][9];
    __shared__ float sM[10][66];

    int tid  = threadIdx.x;
    int lane = tid & 31;
    int g    = tid >> 5;                 // oc sub-group 0..7
    int b    = blockIdx.z >> 2;
    int ocBlock = (blockIdx.z & 3) * 32;
    int h0 = blockIdx.y * 8, w0 = blockIdx.x * 64;
    float inv_sigma = g_inv_sigma;

    for (int i = tid; i < 660; i += 256) {
        int r = i / 66, cc = i % 66;
        int gh = h0 - 1 + r, gw = w0 - 1 + cc;
        float v = 0.f;
        if ((unsigned)gh < (unsigned)HH && (unsigned)gw < (unsigned)WW)
            v = mask[(b*HH + gh)*WW + gw];
        sM[r][cc] = v;
    }

    ull acc[4][8];
    #pragma unroll
    for (int o = 0; o < 4; ++o)
        #pragma unroll
        for (int r = 0; r < 8; ++r) acc[o][r] = 0ull;

    for (int ch = 0; ch < CI; ch += 8) {
        __syncthreads();
        for (int i = tid; i < 5280; i += 256) {
            int c = i / 660, j = i % 660;
            int r = j / 66, cc = j % 66;
            int gh = h0 - 1 + r, gw = w0 - 1 + cc;
            float v = 0.f;
            if ((unsigned)gh < (unsigned)HH && (unsigned)gw < (unsigned)WW)
                v = x[(((size_t)b*CI + ch + c)*HH + gh)*WW + gw] * sM[r][cc];
            sIn[c][r][cc] = v;
        }
        for (int i = tid; i < 2304; i += 256) {
            int c = i / 288, rem = i % 288;
            int oc = rem / 9, k = rem % 9;
            float wv = weight[((ocBlock + oc)*CI + ch + c)*9 + k] * inv_sigma;
            sW2[c][oc][k] = pk(wv, wv);
        }
        __syncthreads();

        #pragma unroll 2
        for (int c = 0; c < 8; ++c) {
            ull wp[4][9];
            #pragma unroll
            for (int o = 0; o < 4; ++o)
                #pragma unroll
                for (int k = 0; k < 9; ++k) wp[o][k] = sW2[c][(g<<2) + o][k];

            ull a0, a1, a2, e0, e1, e2;
            {
                float2 u = *(const float2*)&sIn[c][0][2*lane];
                float2 v = *(const float2*)&sIn[c][0][2*lane + 2];
                a0 = pk(u.x, u.y); a1 = pk(u.y, v.x); a2 = pk(v.x, v.y);
            }
            {
                float2 u = *(const float2*)&sIn[c][1][2*lane];
                float2 v = *(const float2*)&sIn[c][1][2*lane + 2];
                e0 = pk(u.x, u.y); e1 = pk(u.y, v.x); e2 = pk(v.x, v.y);
            }
            #pragma unroll
            for (int r = 0; r < 8; ++r) {
                float2 u = *(const float2*)&sIn[c][r+2][2*lane];
                float2 v = *(const float2*)&sIn[c][r+2][2*lane + 2];
                ull d0 = pk(u.x, u.y), d1 = pk(u.y, v.x), d2 = pk(v.x, v.y);
                #pragma unroll
                for (int o = 0; o < 4; ++o) {
                    ull t = acc[o][r];
                    t = fma2(a0, wp[o][0], t);
                    t = fma2(a1, wp[o][1], t);
                    t = fma2(a2, wp[o][2], t);
                    t = fma2(e0, wp[o][3], t);
                    t = fma2(e1, wp[o][4], t);
                    t = fma2(e2, wp[o][5], t);
                    t = fma2(d0, wp[o][6], t);
                    t = fma2(d1, wp[o][7], t);
                    t = fma2(d2, wp[o][8], t);
                    acc[o][r] = t;
                }
                a0 = e0; a1 = e1; a2 = e2;
                e0 = d0; e1 = d1; e2 = d2;
            }
        }
    }

    float bi[4];
    #pragma unroll
    for (int o = 0; o < 4; ++o) bi[o] = bias[ocBlock + (g<<2) + o];

    #pragma unroll
    for (int r = 0; r < 8; ++r) {
        int h = h0 + r, wq = w0 + 2*lane;
        float2 rr = *(const float2*)&g_ratio[(b*HH + h)*WW + wq];
        #pragma unroll
        for (int o = 0; o < 4; ++o) {
            int oc = ocBlock + (g<<2) + o;
            float lo, hi;
            upk(acc[o][r], lo, hi);
            float2 ov;
            ov.x = rr.x > 0.f ? lo*rr.x + bi[o] : 0.f;
            ov.y = rr.y > 0.f ? hi*rr.y + bi[o] : 0.f;
            *(float2*)&g_x[(((size_t)b*CO + oc)*HH + h)*WW + wq] = ov;
        }
    }
}

// ---------------------------------------------------------------------------
// Partial GDN: y = x / sqrt(beta + gamma @ x^2), f32x2 packed, in-place
// thread = 4 oc x 8 px (4 pairs); 64-px tiles
// ---------------------------------------------------------------------------
#define GDN_GSTRIDE 132
#define GDN_SMEM ((128*GDN_GSTRIDE + 128*64) * 4)

__global__ __launch_bounds__(256, 2)
void gdn_kernel(const float* __restrict__ gamma, const float* __restrict__ beta)
{
    extern __shared__ float sm[];
    float* sG = sm;                       // [c][o], stride 132
    float* sX = sm + 128*GDN_GSTRIDE;     // [c][pix], 64 pix

    int tid = threadIdx.x;
    for (int i = tid; i < 128*128; i += 256) {
        int o = i >> 7, c = i & 127;
        sG[c*GDN_GSTRIDE + o] = gamma[i];
    }
    __syncthreads();

    int og = tid >> 3;          // 0..31 -> 4 oc
    int pg = tid & 7;           // 0..7  -> 8 px
    int o0 = og * 4;
    float be[4];
    #pragma unroll
    for (int oi = 0; oi < 4; ++oi) be[oi] = __ldg(&beta[o0 + oi]);

    const float4* sGv = (const float4*)sG;   // row stride 33
    const float4* sXv = (const float4*)sX;   // row stride 16
    float4* sXw = (float4*)sX;

    const int nTiles = BB * HH * WW / 64;    // 8192
    for (int t = blockIdx.x; t < nTiles; t += gridDim.x) {
        int b = t >> 10;
        int base = (t & 1023) * 64;

        for (int i = tid; i < 128*16; i += 256) {
            int c = i >> 4, pv = i & 15;
            sXw[c*16 + pv] =
                ((const float4*)(g_x + ((size_t)(b*CO + c))*HH*WW + base))[pv];
        }
        __syncthreads();

        ull acc[4][4];
        #pragma unroll
        for (int oi = 0; oi < 4; ++oi)
            #pragma unroll
            for (int p = 0; p < 4; ++p) acc[oi][p] = 0ull;

        #pragma unroll 2
        for (int c = 0; c < 128; ++c) {
            float4 xa = sXv[c*16 + (pg<<1)];
            float4 xb = sXv[c*16 + (pg<<1) + 1];
            ull p0 = pk(xa.x, xa.y), p1 = pk(xa.z, xa.w);
            ull p2 = pk(xb.x, xb.y), p3 = pk(xb.z, xb.w);
            ull s0 = mul2(p0, p0), s1 = mul2(p1, p1);
            ull s2 = mul2(p2, p2), s3 = mul2(p3, p3);
            float4 gv = sGv[c*33 + og];
            ull G[4] = {pk(gv.x, gv.x), pk(gv.y, gv.y), pk(gv.z, gv.z), pk(gv.w, gv.w)};
            #pragma unroll
            for (int oi = 0; oi < 4; ++oi) {
                acc[oi][0] = fma2(G[oi], s0, acc[oi][0]);
                acc[oi][1] = fma2(G[oi], s1, acc[oi][1]);
                acc[oi][2] = fma2(G[oi], s2, acc[oi][2]);
                acc[oi][3] = fma2(G[oi], s3, acc[oi][3]);
            }
        }

        #pragma unroll
        for (int oi = 0; oi < 4; ++oi) {
            #pragma unroll
            for (int j = 0; j < 2; ++j) {
                float4 xv = sXv[(o0 + oi)*16 + (pg<<1) + j];
                float d0, d1, d2, d3;
                upk(acc[oi][2*j],     d0, d1);
                upk(acc[oi][2*j + 1], d2, d3);
                float4 yv;
                yv.x = xv.x * rsqrtf(be[oi] + d0);
                yv.y = xv.y * rsqrtf(be[oi] + d1);
                yv.z = xv.z * rsqrtf(be[oi] + d2);
                yv.w = xv.w * rsqrtf(be[oi] + d3);
                ((float4*)(g_x + ((size_t)(b*CO + o0 + oi))*HH*WW + base))[(pg<<1) + j] = yv;
            }
        }
        __syncthreads();
    }
}

// ---------------------------------------------------------------------------
// Fused 2D DWT (CDF 9/7 analysis), both separable stages in smem
// ---------------------------------------------------------------------------
__global__ __launch_bounds__(256)
void dwt_kernel(float* __restrict__ out)
{
    __shared__ float sT[40][72];
    __shared__ float sLo[16][72];
    __shared__ float sHi[16][72];

    int tid = threadIdx.x;
    int z = blockIdx.z;                       // b*128 + c
    int hb = blockIdx.y * 16, wb = blockIdx.x * 32;
    const float* src = g_x + (size_t)z * HH * WW;

    for (int i = tid; i < 40*72; i += 256) {
        int r = i / 72, cc = i % 72;
        int gr = refl(2*hb - 4 + r, HH);
        int gc = refl(2*wb - 4 + cc, WW);
        sT[r][cc] = src[gr*WW + gc];
    }
    __syncthreads();

    for (int i = tid; i < 16*72; i += 256) {
        int r = i / 72, cc = i % 72;
        float lo = 0.f, hi = 0.f;
        #pragma unroll
        for (int k = 0; k < 9; ++k) lo += c_h0[k] * sT[2*r + k][cc];
        #pragma unroll
        for (int k = 0; k < 7; ++k) hi += c_h1[k] * sT[2*r + k + 1][cc];
        sLo[r][cc] = lo;
        sHi[r][cc] = hi;
    }
    __syncthreads();

    for (int i = tid; i < 16*32; i += 256) {
        int r = i / 32, co = i % 32;
        float ll = 0.f, lh = 0.f, hl = 0.f, hh = 0.f;
        #pragma unroll
        for (int k = 0; k < 9; ++k) {
            ll += c_h0[k] * sLo[r][2*co + k];
            hl += c_h0[k] * sHi[r][2*co + k];
        }
        #pragma unroll
        for (int k = 0; k < 7; ++k) {
            lh += c_h1[k] * sLo[r][2*co + k + 1];
            hh += c_h1[k] * sHi[r][2*co + k + 1];
        }
        size_t idx = (size_t)z*16384 + (size_t)(hb + r)*128 + (wb + co);
        out[OFF_LL + idx] = ll;
        out[OFF_LH + idx] = lh;
        out[OFF_HL + idx] = hl;
        out[OFF_HH + idx] = hh;
    }
}

// ---------------------------------------------------------------------------
// Mask DWT: count>0 composition == OR over reflected 9/7 windows
// ---------------------------------------------------------------------------
__global__ void maskdwt_kernel(float* __restrict__ out)
{
    int idx = blockIdx.x * 256 + threadIdx.x;
    if (idx >= BB*128*128) return;
    int b = idx >> 14, rem = idx & 16383;
    int ho = rem >> 7, wo = rem & 127;

    bool mll = false, mlh = false, mhl = false, mhh = false;
    #pragma unroll
    for (int dr = -4; dr <= 4; ++dr) {
        int gr = refl(2*ho + dr, HH);
        bool row9 = false, row7 = false;
        #pragma unroll
        for (int dc = -4; dc <= 4; ++dc) {
            int gc = refl(2*wo + dc, WW);
            bool v = g_ratio[(b*HH + gr)*WW + gc] > 0.f;
            row9 |= v;
            if (dc >= -3 && dc <= 3) row7 |= v;
        }
        mll |= row9;
        mlh |= row7;
        if (dr >= -3 && dr <= 3) { mhl |= row9; mhh |= row7; }
    }
    out[OFF_MLL + idx] = mll ? 1.f : 0.f;
    out[OFF_MLH + idx] = mlh ? 1.f : 0.f;
    out[OFF_MHL + idx] = mhl ? 1.f : 0.f;
    out[OFF_MHH + idx] = mhh ? 1.f : 0.f;
}

// ---------------------------------------------------------------------------
extern "C" void kernel_launch(void* const* d_in, const int* in_sizes, int n_in,
                              void* d_out, int out_size)
{
    const float* tensor = (const float*)d_in[0];
    const float* mask   = (const float*)d_in[1];
    const float* weight = (const float*)d_in[2];
    const float* bias   = (const float*)d_in[3];
    const float* u      = (const float*)d_in[4];
    const float* beta   = (const float*)d_in[5];
    const float* gamma  = (const float*)d_in[6];
    float* out = (float*)d_out;

    cudaFuncSetAttribute(gdn_kernel,
                         cudaFuncAttributeMaxDynamicSharedMemorySize, GDN_SMEM);

    spectral_kernel<<<1, 256>>>(weight, u);
    ratio_kernel<<<(BB*HH*WW + 255)/256, 256>>>(mask);
    conv_kernel<<<dim3(WW/64, HH/8, BB*4), 256>>>(tensor, mask, weight, bias);
    gdn_kernel<<<296, 256, GDN_SMEM>>>(gamma, beta);
    dwt_kernel<<<dim3(4, 8, BB*CO), 256>>>(out);
    maskdwt_kernel<<<(BB*128*128 + 255)/256, 256>>>(out);
}

// round 6
// speedup vs baseline: 1.4951x; 1.4951x over previous
#include <cuda_runtime.h>
#include <cuda_bf16.h>
#include <math.h>
#include <cstdint>

#define BB 8
#define CI 64
#define CO 128
#define HH 256
#define WW 256

#define SUB (BB*CO*128*128)
#define MSK (BB*128*128)
#define OFF_LL  0
#define OFF_MLL (SUB)
#define OFF_LH  (SUB + MSK)
#define OFF_HL  (2*SUB + MSK)
#define OFF_HH  (3*SUB + MSK)
#define OFF_MLH (4*SUB + MSK)
#define OFF_MHL (4*SUB + 2*MSK)
#define OFF_MHH (4*SUB + 3*MSK)

#define PH 258

// Scratch
__device__ float g_x[(size_t)BB*CO*HH*WW];
__device__ float g_ratio[BB*HH*WW];
__device__ float g_inv_sigma;
__device__ uint4 g_xh4[(size_t)BB*PH*PH*8];   // padded NHWC bf16 hi (8 uint4 = 64ch)
__device__ uint4 g_xl4[(size_t)BB*PH*PH*8];   // lo
// weights: [tap][split][oc][ch] bf16 (ch contiguous)
__device__ __align__(16) unsigned char g_wb[9*2*128*64*2];
// gamma: [split][oc][ch] bf16
__device__ __align__(16) unsigned char g_gb[2*128*128*2];

__constant__ float c_h0[9] = {
    0.026748757410810f, -0.016864118442875f, -0.078223266528990f,
    0.266864118442875f,  0.602949018236360f,  0.266864118442875f,
   -0.078223266528990f, -0.016864118442875f,  0.026748757410810f};
__constant__ float c_h1[7] = {
    0.091271763114250f, -0.057543526228500f, -0.591271763114250f,
    1.115087052457000f, -0.591271763114250f, -0.057543526228500f,
    0.091271763114250f};

__device__ __forceinline__ int refl(int i, int n) {
    return i < 0 ? -i : (i >= n ? 2*n - 2 - i : i);
}
__device__ __forceinline__ uint32_t smem_u32(const void* p) {
    uint32_t a;
    asm("{ .reg .u64 t; cvta.to.shared.u64 t, %1; cvt.u32.u64 %0, t; }" : "=r"(a) : "l"(p));
    return a;
}
__device__ __forceinline__ void cp16(uint32_t s, const void* g) {
    asm volatile("cp.async.cg.shared.global [%0], [%1], 16;" :: "r"(s), "l"(g));
}
__device__ __forceinline__ void cp_commit() {
    asm volatile("cp.async.commit_group;" ::: "memory");
}
__device__ __forceinline__ void cp_wait0() {
    asm volatile("cp.async.wait_group 0;" ::: "memory");
}
__device__ __forceinline__ void ldm_x4(uint32_t* r, uint32_t addr) {
    asm volatile("ldmatrix.sync.aligned.m8n8.x4.shared.b16 {%0,%1,%2,%3}, [%4];"
        : "=r"(r[0]), "=r"(r[1]), "=r"(r[2]), "=r"(r[3]) : "r"(addr));
}
__device__ __forceinline__ void mma_bf16(float* c, const uint32_t* a, const uint32_t* b) {
    asm volatile(
        "mma.sync.aligned.m16n8k16.row.col.f32.bf16.bf16.f32 "
        "{%0,%1,%2,%3}, {%4,%5,%6,%7}, {%8,%9}, {%0,%1,%2,%3};"
        : "+f"(c[0]), "+f"(c[1]), "+f"(c[2]), "+f"(c[3])
        : "r"(a[0]), "r"(a[1]), "r"(a[2]), "r"(a[3]), "r"(b[0]), "r"(b[1]));
}
__device__ __forceinline__ uint32_t pkbf(__nv_bfloat16 a, __nv_bfloat16 b) {
    return (uint32_t)__bfloat16_as_ushort(a) | ((uint32_t)__bfloat16_as_ushort(b) << 16);
}

// ---------------------------------------------------------------------------
// Spectral norm
// ---------------------------------------------------------------------------
__global__ void spectral_kernel(const float* __restrict__ w,
                                const float* __restrict__ u)
{
    __shared__ float sv[576];
    __shared__ float red[256];
    int tid = threadIdx.x;
    float p = 0.f;
    for (int j = tid; j < 576; j += 256) {
        float s = 0.f;
        #pragma unroll 4
        for (int o = 0; o < 128; ++o) s += w[o*576 + j] * u[o];
        sv[j] = s;
        p += s * s;
    }
    red[tid] = p; __syncthreads();
    for (int s = 128; s > 0; s >>= 1) {
        if (tid < s) red[tid] += red[tid + s];
        __syncthreads();
    }
    float vinv = 1.f / (sqrtf(red[0]) + 1e-12f);
    __syncthreads();
    float q = 0.f;
    if (tid < 128) {
        float s = 0.f;
        #pragma unroll 4
        for (int j = 0; j < 576; ++j) s += w[tid*576 + j] * sv[j];
        s *= vinv;
        q = s * s;
    }
    red[tid] = q; __syncthreads();
    for (int s = 128; s > 0; s >>= 1) {
        if (tid < s) red[tid] += red[tid + s];
        __syncthreads();
    }
    if (tid == 0) g_inv_sigma = rsqrtf(red[0]);
}

// ---------------------------------------------------------------------------
// ratio = valid ? 9/msum : 0
// ---------------------------------------------------------------------------
__global__ void ratio_kernel(const float* __restrict__ mask)
{
    int idx = blockIdx.x * 256 + threadIdx.x;
    if (idx >= BB*HH*WW) return;
    int b = idx >> 16, rem = idx & 65535;
    int h = rem >> 8, wq = rem & 255;
    float s = 0.f;
    #pragma unroll
    for (int dh = -1; dh <= 1; ++dh) {
        int gh = h + dh;
        if ((unsigned)gh >= (unsigned)HH) continue;
        #pragma unroll
        for (int dw = -1; dw <= 1; ++dw) {
            int gw = wq + dw;
            if ((unsigned)gw >= (unsigned)WW) continue;
            s += mask[(b*HH + gh)*WW + gw];
        }
    }
    g_ratio[idx] = s > 0.f ? 9.f / fmaxf(s, 1e-8f) : 0.f;
}

// ---------------------------------------------------------------------------
// xprep: padded NHWC bf16 hi/lo of x*mask
// ---------------------------------------------------------------------------
__global__ void xprep_kernel(const float* __restrict__ x,
                             const float* __restrict__ mask)
{
    int idx = blockIdx.x * 256 + threadIdx.x;
    if (idx >= BB*PH*PH*8) return;
    int j = idx & 7;
    int rem = idx >> 3;
    int pw = rem % PH; rem /= PH;
    int ph = rem % PH; int b = rem / PH;
    uint4 h4 = {0,0,0,0}, l4 = {0,0,0,0};
    if (ph > 0 && ph < PH-1 && pw > 0 && pw < PH-1) {
        int h = ph - 1, w = pw - 1;
        float m = mask[(b*HH + h)*WW + w];
        uint32_t hp[4], lp[4];
        #pragma unroll
        for (int k = 0; k < 4; ++k) {
            int c0 = j*8 + 2*k;
            float v0 = x[(((size_t)b*CI + c0)*HH + h)*WW + w] * m;
            float v1 = x[(((size_t)b*CI + c0 + 1)*HH + h)*WW + w] * m;
            __nv_bfloat16 h0 = __float2bfloat16(v0), h1 = __float2bfloat16(v1);
            __nv_bfloat16 e0 = __float2bfloat16(v0 - __bfloat162float(h0));
            __nv_bfloat16 e1 = __float2bfloat16(v1 - __bfloat162float(h1));
            hp[k] = pkbf(h0, h1); lp[k] = pkbf(e0, e1);
        }
        h4.x = hp[0]; h4.y = hp[1]; h4.z = hp[2]; h4.w = hp[3];
        l4.x = lp[0]; l4.y = lp[1]; l4.z = lp[2]; l4.w = lp[3];
    }
    g_xh4[idx] = h4;
    g_xl4[idx] = l4;
}

// ---------------------------------------------------------------------------
// wprep: [tap][split][oc][ch] bf16, spectral-normalized, hi/lo split
// ---------------------------------------------------------------------------
__global__ void wprep_kernel(const float* __restrict__ weight)
{
    int idx = blockIdx.x * 256 + threadIdx.x;
    if (idx >= 9*128*64) return;
    int c = idx & 63, o = (idx >> 6) & 127, tap = idx >> 13;
    float wv = weight[(o*64 + c)*9 + tap] * g_inv_sigma;
    __nv_bfloat16 hv = __float2bfloat16(wv);
    __nv_bfloat16 lv = __float2bfloat16(wv - __bfloat162float(hv));
    __nv_bfloat16* base = (__nv_bfloat16*)g_wb;
    base[((tap*2 + 0)*128 + o)*64 + c] = hv;
    base[((tap*2 + 1)*128 + o)*64 + c] = lv;
}

// ---------------------------------------------------------------------------
// gammaprep: [split][oc][ch] bf16 hi/lo
// ---------------------------------------------------------------------------
__global__ void gammaprep_kernel(const float* __restrict__ gamma)
{
    int idx = blockIdx.x * 256 + threadIdx.x;
    if (idx >= 128*128) return;
    int c = idx & 127, o = idx >> 7;
    float gv = gamma[o*128 + c];
    __nv_bfloat16 hv = __float2bfloat16(gv);
    __nv_bfloat16 lv = __float2bfloat16(gv - __bfloat162float(hv));
    __nv_bfloat16* base = (__nv_bfloat16*)g_gb;
    base[(0*128 + o)*128 + c] = hv;
    base[(1*128 + o)*128 + c] = lv;
}

// ---------------------------------------------------------------------------
// Conv 3x3 as implicit GEMM via mma.sync bf16 split-3 (TN: both k-contiguous)
// CTA = 128 px (half row) x 128 oc.
// ---------------------------------------------------------------------------
#define CV_A_BYTES (2*3*130*128)     // 99840
#define CV_SMEM (CV_A_BYTES + 2*2*128*128)   // + 65536 = 165376

__global__ __launch_bounds__(256)
void conv_mma_kernel(const float* __restrict__ bias)
{
    extern __shared__ unsigned char dsm[];
    uint32_t sA = smem_u32(dsm);
    uint32_t sB = sA + CV_A_BYTES;
    float* sD = (float*)dsm;          // reuse A region in epilogue

    int tid = threadIdx.x;
    int lane = tid & 31, wid = tid >> 5;
    int wm = (wid & 3) * 32;          // warp m offset (px)
    int wn = (wid >> 2) * 64;         // warp n offset (oc)

    int t = blockIdx.x;
    int b = t >> 9, h = (t & 511) >> 1, q = t & 1;

    // stage A: both splits, 3 rows, 130 px
    for (int i = tid; i < 6240; i += 256) {
        int s = i / 3120, rem = i % 3120;
        int r = rem / 1040; rem %= 1040;
        int p = rem >> 3, c = rem & 7;
        const uint4* src = (s ? g_xl4 : g_xh4)
            + ((size_t)(b*PH + h + r))*PH*8 + (size_t)(q*128 + p)*8 + c;
        cp16(sA + ((s*3 + r)*130 + p)*128 + ((c ^ (p & 7)) << 4), src);
    }
    // stage B tap 0 -> buf 0
    for (int i = tid; i < 2048; i += 256) {
        int s = i >> 10, o = (i >> 3) & 127, c = i & 7;
        const unsigned char* src = g_wb + (size_t)(((0*2 + s)*128 + o)*64 + c*8)*2;
        cp16(sB + 0*32768 + s*16384 + o*128 + ((c ^ (o & 7)) << 4), src);
    }
    cp_commit();

    float acc[2][8][4];
    #pragma unroll
    for (int ma = 0; ma < 2; ++ma)
        #pragma unroll
        for (int nt = 0; nt < 8; ++nt)
            #pragma unroll
            for (int k = 0; k < 4; ++k) acc[ma][nt][k] = 0.f;

    for (int tap = 0; tap < 9; ++tap) {
        cp_wait0();
        __syncthreads();
        if (tap < 8) {
            int nt2 = tap + 1;
            uint32_t bu = (uint32_t)(nt2 & 1);
            for (int i = tid; i < 2048; i += 256) {
                int s = i >> 10, o = (i >> 3) & 127, c = i & 7;
                const unsigned char* src = g_wb + (size_t)(((nt2*2 + s)*128 + o)*64 + c*8)*2;
                cp16(sB + bu*32768 + s*16384 + o*128 + ((c ^ (o & 7)) << 4), src);
            }
            cp_commit();
        }
        int dh = tap / 3, dw = tap % 3;
        uint32_t bbase = sB + (uint32_t)(tap & 1)*32768;
        #pragma unroll
        for (int pass = 0; pass < 3; ++pass) {
            int sa = (pass == 1) ? 1 : 0;
            int sb = (pass == 2) ? 1 : 0;
            uint32_t abase = sA + (uint32_t)(sa*3 + dh)*130*128;
            #pragma unroll
            for (int ks = 0; ks < 4; ++ks) {
                uint32_t a[2][4];
                #pragma unroll
                for (int ma = 0; ma < 2; ++ma) {
                    int m = wm + ma*16 + (lane & 7) + ((lane >> 3) & 1)*8;
                    int p = m + dw;
                    int ch = 2*ks + (lane >> 4);
                    ldm_x4(a[ma], abase + p*128 + ((ch ^ (p & 7)) << 4));
                }
                uint32_t bf[8][2];
                #pragma unroll
                for (int nb = 0; nb < 4; ++nb) {
                    int n = wn + nb*16 + (lane & 7) + ((lane >> 4) << 3);
                    int ch = 2*ks + ((lane >> 3) & 1);
                    uint32_t r4[4];
                    ldm_x4(r4, bbase + sb*16384 + n*128 + ((ch ^ (n & 7)) << 4));
                    bf[2*nb][0] = r4[0]; bf[2*nb][1] = r4[1];
                    bf[2*nb+1][0] = r4[2]; bf[2*nb+1][1] = r4[3];
                }
                #pragma unroll
                for (int ma = 0; ma < 2; ++ma)
                    #pragma unroll
                    for (int nt = 0; nt < 8; ++nt)
                        mma_bf16(acc[ma][nt], a[ma], bf[nt]);
            }
        }
        __syncthreads();
    }

    // epilogue: acc (m=px, n=oc) -> smem [oc][px] -> coalesced planar writes
    #pragma unroll
    for (int ma = 0; ma < 2; ++ma)
        #pragma unroll
        for (int nt = 0; nt < 8; ++nt) {
            int r = wm + ma*16 + (lane >> 2);
            int cb = wn + nt*8 + 2*(lane & 3);
            sD[cb*129 + r]           = acc[ma][nt][0];
            sD[(cb + 1)*129 + r]     = acc[ma][nt][1];
            sD[cb*129 + r + 8]       = acc[ma][nt][2];
            sD[(cb + 1)*129 + r + 8] = acc[ma][nt][3];
        }
    __syncthreads();
    int wq0 = q*128;
    const float* rp = g_ratio + (b*HH + h)*WW + wq0;
    float* outbase = g_x + (size_t)b*CO*HH*WW + h*WW + wq0;
    for (int i = tid; i < 16384; i += 256) {
        int o = i >> 7, p = i & 127;
        float ratio = __ldg(rp + p);
        float v = ratio > 0.f ? sD[o*129 + p]*ratio + __ldg(bias + o) : 0.f;
        outbase[(size_t)o*(HH*WW) + p] = v;
    }
}

// ---------------------------------------------------------------------------
// GDN as GEMM via mma.sync: D[px][oc] = xsq[px][ch] @ gamma[oc][ch]^T, split-3
// ---------------------------------------------------------------------------
#define GDN_A_BYTES 69632
#define GDN_SMEM (GDN_A_BYTES + 2*128*256)   // 135168

__global__ __launch_bounds__(256)
void gdn_mma_kernel(const float* __restrict__ beta)
{
    extern __shared__ unsigned char dsm[];
    uint32_t sA = smem_u32(dsm);
    uint32_t sB = sA + GDN_A_BYTES;
    float* sD = (float*)dsm;

    int tid = threadIdx.x;
    int lane = tid & 31, wid = tid >> 5;
    int wm = (wid & 3) * 32;
    int wn = (wid >> 2) * 64;

    int t = blockIdx.x;
    int b = t >> 9;
    int pxb = (t & 511) * 128;

    // stage gamma (both splits)
    for (int i = tid; i < 4096; i += 256) {
        int s = i >> 11, o = (i >> 4) & 127, c = i & 15;
        const unsigned char* src = g_gb + (size_t)((s*128 + o)*128 + c*8)*2;
        cp16(sB + s*32768 + o*256 + ((c ^ (o & 7)) << 4), src);
    }
    cp_commit();

    // stage A = split(x^2)
    const float* xbase = g_x + (size_t)b*CO*HH*WW + pxb;
    for (int i = tid; i < 16384; i += 256) {
        int ch = i >> 7, p = i & 127;
        float v = xbase[(size_t)ch*(HH*WW) + p];
        float s = v*v;
        __nv_bfloat16 hv = __float2bfloat16(s);
        __nv_bfloat16 lv = __float2bfloat16(s - __bfloat162float(hv));
        int cidx = ch >> 3, e = ch & 7;
        uint32_t off = (uint32_t)p*256 + (uint32_t)((cidx ^ (p & 7)) << 4) + e*2;
        *(__nv_bfloat16*)(dsm + off) = hv;
        *(__nv_bfloat16*)(dsm + 32768 + off) = lv;
    }
    cp_wait0();
    __syncthreads();

    float acc[2][8][4];
    #pragma unroll
    for (int ma = 0; ma < 2; ++ma)
        #pragma unroll
        for (int nt = 0; nt < 8; ++nt)
            #pragma unroll
            for (int k = 0; k < 4; ++k) acc[ma][nt][k] = 0.f;

    #pragma unroll
    for (int pass = 0; pass < 3; ++pass) {
        int sa = (pass == 1) ? 1 : 0;
        int sb = (pass == 2) ? 1 : 0;
        uint32_t abase = sA + (uint32_t)sa*32768;
        uint32_t bbase = sB + (uint32_t)sb*32768;
        #pragma unroll
        for (int ks = 0; ks < 8; ++ks) {
            uint32_t a[2][4];
            #pragma unroll
            for (int ma = 0; ma < 2; ++ma) {
                int p = wm + ma*16 + (lane & 7) + ((lane >> 3) & 1)*8;
                int ch = 2*ks + (lane >> 4);
                ldm_x4(a[ma], abase + p*256 + ((ch ^ (p & 7)) << 4));
            }
            uint32_t bf[8][2];
            #pragma unroll
            for (int nb = 0; nb < 4; ++nb) {
                int n = wn + nb*16 + (lane & 7) + ((lane >> 4) << 3);
                int ch = 2*ks + ((lane >> 3) & 1);
                uint32_t r4[4];
                ldm_x4(r4, bbase + n*256 + ((ch ^ (n & 7)) << 4));
                bf[2*nb][0] = r4[0]; bf[2*nb][1] = r4[1];
                bf[2*nb+1][0] = r4[2]; bf[2*nb+1][1] = r4[3];
            }
            #pragma unroll
            for (int ma = 0; ma < 2; ++ma)
                #pragma unroll
                for (int nt = 0; nt < 8; ++nt)
                    mma_bf16(acc[ma][nt], a[ma], bf[nt]);
        }
    }
    __syncthreads();

    // epilogue
    #pragma unroll
    for (int ma = 0; ma < 2; ++ma)
        #pragma unroll
        for (int nt = 0; nt < 8; ++nt) {
            int r = wm + ma*16 + (lane >> 2);
            int cb = wn + nt*8 + 2*(lane & 3);
            sD[cb*129 + r]           = acc[ma][nt][0];
            sD[(cb + 1)*129 + r]     = acc[ma][nt][1];
            sD[cb*129 + r + 8]       = acc[ma][nt][2];
            sD[(cb + 1)*129 + r + 8] = acc[ma][nt][3];
        }
    __syncthreads();
    float* ybase = g_x + (size_t)b*CO*HH*WW + pxb;
    for (int i = tid; i < 16384; i += 256) {
        int o = i >> 7, p = i & 127;
        float xx = ybase[(size_t)o*(HH*WW) + p];
        ybase[(size_t)o*(HH*WW) + p] =
            xx * rsqrtf(__ldg(beta + o) + sD[o*129 + p]);
    }
}

// ---------------------------------------------------------------------------
// Fused 2D DWT (CDF 9/7 analysis)
// ---------------------------------------------------------------------------
__global__ __launch_bounds__(256)
void dwt_kernel(float* __restrict__ out)
{
    __shared__ float sT[40][72];
    __shared__ float sLo[16][72];
    __shared__ float sHi[16][72];

    int tid = threadIdx.x;
    int z = blockIdx.z;
    int hb = blockIdx.y * 16, wb = blockIdx.x * 32;
    const float* src = g_x + (size_t)z * HH * WW;

    for (int i = tid; i < 40*72; i += 256) {
        int r = i / 72, cc = i % 72;
        int gr = refl(2*hb - 4 + r, HH);
        int gc = refl(2*wb - 4 + cc, WW);
        sT[r][cc] = src[gr*WW + gc];
    }
    __syncthreads();

    for (int i = tid; i < 16*72; i += 256) {
        int r = i / 72, cc = i % 72;
        float lo = 0.f, hi = 0.f;
        #pragma unroll
        for (int k = 0; k < 9; ++k) lo += c_h0[k] * sT[2*r + k][cc];
        #pragma unroll
        for (int k = 0; k < 7; ++k) hi += c_h1[k] * sT[2*r + k + 1][cc];
        sLo[r][cc] = lo;
        sHi[r][cc] = hi;
    }
    __syncthreads();

    for (int i = tid; i < 16*32; i += 256) {
        int r = i / 32, co = i % 32;
        float ll = 0.f, lh = 0.f, hl = 0.f, hh = 0.f;
        #pragma unroll
        for (int k = 0; k < 9; ++k) {
            ll += c_h0[k] * sLo[r][2*co + k];
            hl += c_h0[k] * sHi[r][2*co + k];
        }
        #pragma unroll
        for (int k = 0; k < 7; ++k) {
            lh += c_h1[k] * sLo[r][2*co + k + 1];
            hh += c_h1[k] * sHi[r][2*co + k + 1];
        }
        size_t idx = (size_t)z*16384 + (size_t)(hb + r)*128 + (wb + co);
        out[OFF_LL + idx] = ll;
        out[OFF_LH + idx] = lh;
        out[OFF_HL + idx] = hl;
        out[OFF_HH + idx] = hh;
    }
}

// ---------------------------------------------------------------------------
// Mask DWT: OR over reflected 9/7 windows
// ---------------------------------------------------------------------------
__global__ void maskdwt_kernel(float* __restrict__ out)
{
    int idx = blockIdx.x * 256 + threadIdx.x;
    if (idx >= BB*128*128) return;
    int b = idx >> 14, rem = idx & 16383;
    int ho = rem >> 7, wo = rem & 127;

    bool mll = false, mlh = false, mhl = false, mhh = false;
    #pragma unroll
    for (int dr = -4; dr <= 4; ++dr) {
        int gr = refl(2*ho + dr, HH);
        bool row9 = false, row7 = false;
        #pragma unroll
        for (int dc = -4; dc <= 4; ++dc) {
            int gc = refl(2*wo + dc, WW);
            bool v = g_ratio[(b*HH + gr)*WW + gc] > 0.f;
            row9 |= v;
            if (dc >= -3 && dc <= 3) row7 |= v;
        }
        mll |= row9;
        mlh |= row7;
        if (dr >= -3 && dr <= 3) { mhl |= row9; mhh |= row7; }
    }
    out[OFF_MLL + idx] = mll ? 1.f : 0.f;
    out[OFF_MLH + idx] = mlh ? 1.f : 0.f;
    out[OFF_MHL + idx] = mhl ? 1.f : 0.f;
    out[OFF_MHH + idx] = mhh ? 1.f : 0.f;
}

// ---------------------------------------------------------------------------
extern "C" void kernel_launch(void* const* d_in, const int* in_sizes, int n_in,
                              void* d_out, int out_size)
{
    const float* tensor = (const float*)d_in[0];
    const float* mask   = (const float*)d_in[1];
    const float* weight = (const float*)d_in[2];
    const float* bias   = (const float*)d_in[3];
    const float* u      = (const float*)d_in[4];
    const float* beta   = (const float*)d_in[5];
    const float* gamma  = (const float*)d_in[6];
    float* out = (float*)d_out;

    cudaFuncSetAttribute(conv_mma_kernel,
                         cudaFuncAttributeMaxDynamicSharedMemorySize, CV_SMEM);
    cudaFuncSetAttribute(gdn_mma_kernel,
                         cudaFuncAttributeMaxDynamicSharedMemorySize, GDN_SMEM);

    spectral_kernel<<<1, 256>>>(weight, u);
    ratio_kernel<<<(BB*HH*WW + 255)/256, 256>>>(mask);
    xprep_kernel<<<(BB*PH*PH*8 + 255)/256, 256>>>(tensor, mask);
    wprep_kernel<<<(9*128*64 + 255)/256, 256>>>(weight);
    gammaprep_kernel<<<(128*128 + 255)/256, 256>>>(gamma);
    conv_mma_kernel<<<4096, 256, CV_SMEM>>>(bias);
    gdn_mma_kernel<<<4096, 256, GDN_SMEM>>>(beta);
    dwt_kernel<<<dim3(4, 8, BB*CO), 256>>>(out);
    maskdwt_kernel<<<(BB*128*128 + 255)/256, 256>>>(out);
}

// round 8
// speedup vs baseline: 2.5297x; 1.6920x over previous
#include <cuda_runtime.h>
#include <cuda_fp16.h>
#include <math.h>
#include <cstdint>

#define BB 8
#define CI 64
#define CO 128
#define HH 256
#define WW 256

#define SUB (BB*CO*128*128)
#define MSK (BB*128*128)
#define OFF_LL  0
#define OFF_MLL (SUB)
#define OFF_LH  (SUB + MSK)
#define OFF_HL  (2*SUB + MSK)
#define OFF_HH  (3*SUB + MSK)
#define OFF_MLH (4*SUB + MSK)
#define OFF_MHL (4*SUB + 2*MSK)
#define OFF_MHH (4*SUB + 3*MSK)

#define PH 258

// Scratch
__device__ float g_x[(size_t)BB*CO*HH*WW];
__device__ float g_ratio[BB*HH*WW];
__device__ float g_inv_sigma;
__device__ uint4 g_xh4[(size_t)BB*PH*PH*8];   // padded NHWC fp16 hi (8 uint4 = 64ch)
__device__ uint4 g_xl4[(size_t)BB*PH*PH*8];   // lo
__device__ __half g_wh[9*128*64];             // [tap][oc][ch] fp16 (spectral-normalized)
__device__ __half g_gh[128*128];              // gamma [oc][ch] fp16

__constant__ float c_h0[9] = {
    0.026748757410810f, -0.016864118442875f, -0.078223266528990f,
    0.266864118442875f,  0.602949018236360f,  0.266864118442875f,
   -0.078223266528990f, -0.016864118442875f,  0.026748757410810f};
__constant__ float c_h1[7] = {
    0.091271763114250f, -0.057543526228500f, -0.591271763114250f,
    1.115087052457000f, -0.591271763114250f, -0.057543526228500f,
    0.091271763114250f};

__device__ __forceinline__ int refl(int i, int n) {
    return i < 0 ? -i : (i >= n ? 2*n - 2 - i : i);
}
__device__ __forceinline__ uint32_t smem_u32(const void* p) {
    uint32_t a;
    asm("{ .reg .u64 t; cvta.to.shared.u64 t, %1; cvt.u32.u64 %0, t; }" : "=r"(a) : "l"(p));
    return a;
}
__device__ __forceinline__ void cp16(uint32_t s, const void* g) {
    asm volatile("cp.async.cg.shared.global [%0], [%1], 16;" :: "r"(s), "l"(g));
}
__device__ __forceinline__ void cp_commit() {
    asm volatile("cp.async.commit_group;" ::: "memory");
}
__device__ __forceinline__ void cp_wait0() {
    asm volatile("cp.async.wait_group 0;" ::: "memory");
}
__device__ __forceinline__ void ldm_x4(uint32_t* r, uint32_t addr) {
    asm volatile("ldmatrix.sync.aligned.m8n8.x4.shared.b16 {%0,%1,%2,%3}, [%4];"
        : "=r"(r[0]), "=r"(r[1]), "=r"(r[2]), "=r"(r[3]) : "r"(addr));
}
__device__ __forceinline__ void mma_f16(float* c, const uint32_t* a, const uint32_t* b) {
    asm volatile(
        "mma.sync.aligned.m16n8k16.row.col.f32.f16.f16.f32 "
        "{%0,%1,%2,%3}, {%4,%5,%6,%7}, {%8,%9}, {%0,%1,%2,%3};"
        : "+f"(c[0]), "+f"(c[1]), "+f"(c[2]), "+f"(c[3])
        : "r"(a[0]), "r"(a[1]), "r"(a[2]), "r"(a[3]), "r"(b[0]), "r"(b[1]));
}
__device__ __forceinline__ uint32_t pkh(__half a, __half b) {
    return (uint32_t)__half_as_ushort(a) | ((uint32_t)__half_as_ushort(b) << 16);
}

// ---------------------------------------------------------------------------
// Spectral norm
// ---------------------------------------------------------------------------
__global__ void spectral_kernel(const float* __restrict__ w,
                                const float* __restrict__ u)
{
    __shared__ float sv[576];
    __shared__ float red[256];
    int tid = threadIdx.x;
    float p = 0.f;
    for (int j = tid; j < 576; j += 256) {
        float s = 0.f;
        #pragma unroll 4
        for (int o = 0; o < 128; ++o) s += w[o*576 + j] * u[o];
        sv[j] = s;
        p += s * s;
    }
    red[tid] = p; __syncthreads();
    for (int s = 128; s > 0; s >>= 1) {
        if (tid < s) red[tid] += red[tid + s];
        __syncthreads();
    }
    float vinv = 1.f / (sqrtf(red[0]) + 1e-12f);
    __syncthreads();
    float q = 0.f;
    if (tid < 128) {
        float s = 0.f;
        #pragma unroll 4
        for (int j = 0; j < 576; ++j) s += w[tid*576 + j] * sv[j];
        s *= vinv;
        q = s * s;
    }
    red[tid] = q; __syncthreads();
    for (int s = 128; s > 0; s >>= 1) {
        if (tid < s) red[tid] += red[tid + s];
        __syncthreads();
    }
    if (tid == 0) g_inv_sigma = rsqrtf(red[0]);
}

// ---------------------------------------------------------------------------
// xprep: padded NHWC fp16 hi/lo of x*mask
// ---------------------------------------------------------------------------
__global__ void xprep_kernel(const float* __restrict__ x,
                             const float* __restrict__ mask)
{
    int idx = blockIdx.x * 256 + threadIdx.x;
    if (idx >= BB*PH*PH*8) return;
    int j = idx & 7;
    int rem = idx >> 3;
    int pw = rem % PH; rem /= PH;
    int ph = rem % PH; int b = rem / PH;
    uint4 h4 = {0,0,0,0}, l4 = {0,0,0,0};
    if (ph > 0 && ph < PH-1 && pw > 0 && pw < PH-1) {
        int h = ph - 1, w = pw - 1;
        float m = mask[(b*HH + h)*WW + w];
        uint32_t hp[4], lp[4];
        #pragma unroll
        for (int k = 0; k < 4; ++k) {
            int c0 = j*8 + 2*k;
            float v0 = x[(((size_t)b*CI + c0)*HH + h)*WW + w] * m;
            float v1 = x[(((size_t)b*CI + c0 + 1)*HH + h)*WW + w] * m;
            __half h0 = __float2half_rn(v0), h1 = __float2half_rn(v1);
            __half e0 = __float2half_rn(v0 - __half2float(h0));
            __half e1 = __float2half_rn(v1 - __half2float(h1));
            hp[k] = pkh(h0, h1); lp[k] = pkh(e0, e1);
        }
        h4.x = hp[0]; h4.y = hp[1]; h4.z = hp[2]; h4.w = hp[3];
        l4.x = lp[0]; l4.y = lp[1]; l4.z = lp[2]; l4.w = lp[3];
    }
    g_xh4[idx] = h4;
    g_xl4[idx] = l4;
}

// ---------------------------------------------------------------------------
// wprep: [tap][oc][ch] fp16, spectral-normalized
// ---------------------------------------------------------------------------
__global__ void wprep_kernel(const float* __restrict__ weight)
{
    int idx = blockIdx.x * 256 + threadIdx.x;
    if (idx >= 9*128*64) return;
    int c = idx & 63, o = (idx >> 6) & 127, tap = idx >> 13;
    float wv = weight[(o*64 + c)*9 + tap] * g_inv_sigma;
    g_wh[(tap*128 + o)*64 + c] = __float2half_rn(wv);
}

// ---------------------------------------------------------------------------
// gammaprep: [oc][ch] fp16
// ---------------------------------------------------------------------------
__global__ void gammaprep_kernel(const float* __restrict__ gamma)
{
    int idx = blockIdx.x * 256 + threadIdx.x;
    if (idx >= 128*128) return;
    g_gh[idx] = __float2half_rn(gamma[idx]);
}

// ---------------------------------------------------------------------------
// Conv 3x3 as implicit GEMM via mma.sync fp16 2-pass (ext-K = [Xh|Xl]·[Wh|Wh])
// CTA = 128 px (half row) x 128 oc.  Also computes the partial-conv ratio.
// ---------------------------------------------------------------------------
#define CV_A_BYTES (3*130*256)               // 99840
#define CV_SMEM (CV_A_BYTES + 2*128*128)     // + 32768 = 132608

__global__ __launch_bounds__(256)
void conv_mma_kernel(const float* __restrict__ bias,
                     const float* __restrict__ mask)
{
    extern __shared__ unsigned char dsm[];
    uint32_t sA = smem_u32(dsm);
    uint32_t sB = sA + CV_A_BYTES;
    float* sD = (float*)dsm;                  // reuse A region in epilogue
    float* sRat = (float*)(dsm + CV_A_BYTES); // reuse B region in epilogue

    int tid = threadIdx.x;
    int lane = tid & 31, wid = tid >> 5;
    int wm = (wid & 3) * 32;
    int wn = (wid >> 2) * 64;

    int t = blockIdx.x;
    int b = t >> 9, h = (t & 511) >> 1, q = t & 1;

    // stage A: 3 rows x 130 px x 256B (hi chunks 0-7, lo chunks 8-15)
    for (int i = tid; i < 6240; i += 256) {
        int r = i / 2080, rem = i % 2080;
        int p = rem >> 4, c = rem & 15;
        size_t pix = ((size_t)(b*PH + h + r))*PH*8 + (size_t)(q*128 + p)*8;
        const uint4* src = (c < 8) ? (g_xh4 + pix + c) : (g_xl4 + pix + (c - 8));
        cp16(sA + (r*130 + p)*256 + ((c ^ (p & 7)) << 4), src);
    }
    // stage B tap 0 -> buf 0 (single split, 16KB)
    for (int i = tid; i < 1024; i += 256) {
        int o = i >> 3, c = i & 7;
        const __half* src = g_wh + (size_t)(0*128 + o)*64 + c*8;
        cp16(sB + 0*16384 + o*128 + ((c ^ (o & 7)) << 4), src);
    }
    cp_commit();

    float acc[2][8][4];
    #pragma unroll
    for (int ma = 0; ma < 2; ++ma)
        #pragma unroll
        for (int nt = 0; nt < 8; ++nt)
            #pragma unroll
            for (int k = 0; k < 4; ++k) acc[ma][nt][k] = 0.f;

    for (int tap = 0; tap < 9; ++tap) {
        cp_wait0();
        __syncthreads();
        if (tap < 8) {
            int nt2 = tap + 1;
            uint32_t bu = (uint32_t)(nt2 & 1);
            for (int i = tid; i < 1024; i += 256) {
                int o = i >> 3, c = i & 7;
                const __half* src = g_wh + (size_t)(nt2*128 + o)*64 + c*8;
                cp16(sB + bu*16384 + o*128 + ((c ^ (o & 7)) << 4), src);
            }
            cp_commit();
        }
        int dh = tap / 3, dw = tap % 3;
        uint32_t abase = sA + (uint32_t)(dh*130)*256;
        uint32_t bbase = sB + (uint32_t)(tap & 1)*16384;
        #pragma unroll
        for (int ks = 0; ks < 8; ++ks) {
            uint32_t a[2][4];
            #pragma unroll
            for (int ma = 0; ma < 2; ++ma) {
                int m = wm + ma*16 + (lane & 7) + ((lane >> 3) & 1)*8;
                int p = m + dw;
                int ch = 2*ks + (lane >> 4);            // 0..15 ext-K chunk
                ldm_x4(a[ma], abase + p*256 + ((ch ^ (p & 7)) << 4));
            }
            uint32_t bf[8][2];
            #pragma unroll
            for (int nb = 0; nb < 4; ++nb) {
                int n = wn + nb*16 + (lane & 7) + ((lane >> 4) << 3);
                int ch = (2*ks + ((lane >> 3) & 1)) & 7; // Wh repeats
                uint32_t r4[4];
                ldm_x4(r4, bbase + n*128 + ((ch ^ (n & 7)) << 4));
                bf[2*nb][0] = r4[0]; bf[2*nb][1] = r4[1];
                bf[2*nb+1][0] = r4[2]; bf[2*nb+1][1] = r4[3];
            }
            #pragma unroll
            for (int ma = 0; ma < 2; ++ma)
                #pragma unroll
                for (int nt = 0; nt < 8; ++nt)
                    mma_f16(acc[ma][nt], a[ma], bf[nt]);
        }
        __syncthreads();
    }

    // epilogue: acc -> smem [oc][px]; compute partial-conv ratio; write planar
    #pragma unroll
    for (int ma = 0; ma < 2; ++ma)
        #pragma unroll
        for (int nt = 0; nt < 8; ++nt) {
            int r = wm + ma*16 + (lane >> 2);
            int cb = wn + nt*8 + 2*(lane & 3);
            sD[cb*129 + r]           = acc[ma][nt][0];
            sD[(cb + 1)*129 + r]     = acc[ma][nt][1];
            sD[cb*129 + r + 8]       = acc[ma][nt][2];
            sD[(cb + 1)*129 + r + 8] = acc[ma][nt][3];
        }
    int wq0 = q*128;
    if (tid < 128) {
        int wq = wq0 + tid;
        float s = 0.f;
        #pragma unroll
        for (int dh = -1; dh <= 1; ++dh) {
            int gh = h + dh;
            if ((unsigned)gh >= (unsigned)HH) continue;
            #pragma unroll
            for (int dw = -1; dw <= 1; ++dw) {
                int gw = wq + dw;
                if ((unsigned)gw >= (unsigned)WW) continue;
                s += mask[(b*HH + gh)*WW + gw];
            }
        }
        float ratio = s > 0.f ? 9.f / fmaxf(s, 1e-8f) : 0.f;
        sRat[tid] = ratio;
        g_ratio[(b*HH + h)*WW + wq] = ratio;
    }
    __syncthreads();
    float* outbase = g_x + (size_t)b*CO*HH*WW + h*WW + wq0;
    for (int i = tid; i < 16384; i += 256) {
        int o = i >> 7, p = i & 127;
        float ratio = sRat[p];
        float v = ratio > 0.f ? sD[o*129 + p]*ratio + __ldg(bias + o) : 0.f;
        outbase[(size_t)o*(HH*WW) + p] = v;
    }
}

// ---------------------------------------------------------------------------
// GDN as GEMM via mma.sync fp16 2-pass: ext-K = [Xh2|Xl2]·[Gh|Gh], K=256
// ---------------------------------------------------------------------------
#define GDN_A_BYTES 66048
#define GDN_SMEM (GDN_A_BYTES + 128*256)     // + 32768 = 98816

__global__ __launch_bounds__(256)
void gdn_mma_kernel(const float* __restrict__ beta)
{
    extern __shared__ unsigned char dsm[];
    uint32_t sA = smem_u32(dsm);
    uint32_t sB = sA + GDN_A_BYTES;
    float* sD = (float*)dsm;

    int tid = threadIdx.x;
    int lane = tid & 31, wid = tid >> 5;
    int wm = (wid & 3) * 32;
    int wn = (wid >> 2) * 64;

    int t = blockIdx.x;
    int b = t >> 9;
    int pxb = (t & 511) * 128;

    // stage gamma (single split, 32KB)
    for (int i = tid; i < 2048; i += 256) {
        int o = i >> 4, c = i & 15;
        const __half* src = g_gh + (size_t)o*128 + c*8;
        cp16(sB + o*256 + ((c ^ (o & 7)) << 4), src);
    }
    cp_commit();

    // stage A = split(x^2): row = 512B: hi chunks 0-15, lo chunks 16-31
    const float* xbase = g_x + (size_t)b*CO*HH*WW + pxb;
    for (int i = tid; i < 16384; i += 256) {
        int ch = i >> 7, p = i & 127;
        float v = xbase[(size_t)ch*(HH*WW) + p];
        float s = v*v;
        __half hv = __float2half_rn(s);
        __half lv = __float2half_rn(s - __half2float(hv));
        int cidx = ch >> 3, e = ch & 7;
        uint32_t hoff = (uint32_t)p*512 + (uint32_t)((cidx ^ (p & 7)) << 4) + e*2;
        *(__half*)(dsm + hoff) = hv;
        *(__half*)(dsm + hoff + 256) = lv;   // chunk+16: swizzle consistent (+256B)
    }
    cp_wait0();
    __syncthreads();

    float acc[2][8][4];
    #pragma unroll
    for (int ma = 0; ma < 2; ++ma)
        #pragma unroll
        for (int nt = 0; nt < 8; ++nt)
            #pragma unroll
            for (int k = 0; k < 4; ++k) acc[ma][nt][k] = 0.f;

    #pragma unroll
    for (int ks = 0; ks < 16; ++ks) {
        uint32_t a[2][4];
        #pragma unroll
        for (int ma = 0; ma < 2; ++ma) {
            int p = wm + ma*16 + (lane & 7) + ((lane >> 3) & 1)*8;
            int ch = 2*ks + (lane >> 4);                // 0..31
            ldm_x4(a[ma], sA + p*512 + ((ch ^ (p & 7)) << 4));
        }
        uint32_t bf[8][2];
        #pragma unroll
        for (int nb = 0; nb < 4; ++nb) {
            int n = wn + nb*16 + (lane & 7) + ((lane >> 4) << 3);
            int ch = (2*ks + ((lane >> 3) & 1)) & 15;   // Gh repeats
            uint32_t r4[4];
            ldm_x4(r4, sB + n*256 + ((ch ^ (n & 7)) << 4));
            bf[2*nb][0] = r4[0]; bf[2*nb][1] = r4[1];
            bf[2*nb+1][0] = r4[2]; bf[2*nb+1][1] = r4[3];
        }
        #pragma unroll
        for (int ma = 0; ma < 2; ++ma)
            #pragma unroll
            for (int nt = 0; nt < 8; ++nt)
                mma_f16(acc[ma][nt], a[ma], bf[nt]);
    }
    __syncthreads();

    // epilogue
    #pragma unroll
    for (int ma = 0; ma < 2; ++ma)
        #pragma unroll
        for (int nt = 0; nt < 8; ++nt) {
            int r = wm + ma*16 + (lane >> 2);
            int cb = wn + nt*8 + 2*(lane & 3);
            sD[cb*129 + r]           = acc[ma][nt][0];
            sD[(cb + 1)*129 + r]     = acc[ma][nt][1];
            sD[cb*129 + r + 8]       = acc[ma][nt][2];
            sD[(cb + 1)*129 + r + 8] = acc[ma][nt][3];
        }
    __syncthreads();
    float* ybase = g_x + (size_t)b*CO*HH*WW + pxb;
    for (int i = tid; i < 16384; i += 256) {
        int o = i >> 7, p = i & 127;
        float xx = ybase[(size_t)o*(HH*WW) + p];
        ybase[(size_t)o*(HH*WW) + p] =
            xx * rsqrtf(__ldg(beta + o) + sD[o*129 + p]);
    }
}

// ---------------------------------------------------------------------------
// Fused 2D DWT (CDF 9/7 analysis)
// ---------------------------------------------------------------------------
__global__ __launch_bounds__(256)
void dwt_kernel(float* __restrict__ out)
{
    __shared__ float sT[40][72];
    __shared__ float sLo[16][72];
    __shared__ float sHi[16][72];

    int tid = threadIdx.x;
    int z = blockIdx.z;
    int hb = blockIdx.y * 16, wb = blockIdx.x * 32;
    const float* src = g_x + (size_t)z * HH * WW;

    for (int i = tid; i < 40*72; i += 256) {
        int r = i / 72, cc = i % 72;
        int gr = refl(2*hb - 4 + r, HH);
        int gc = refl(2*wb - 4 + cc, WW);
        sT[r][cc] = src[gr*WW + gc];
    }
    __syncthreads();

    for (int i = tid; i < 16*72; i += 256) {
        int r = i / 72, cc = i % 72;
        float lo = 0.f, hi = 0.f;
        #pragma unroll
        for (int k = 0; k < 9; ++k) lo += c_h0[k] * sT[2*r + k][cc];
        #pragma unroll
        for (int k = 0; k < 7; ++k) hi += c_h1[k] * sT[2*r + k + 1][cc];
        sLo[r][cc] = lo;
        sHi[r][cc] = hi;
    }
    __syncthreads();

    for (int i = tid; i < 16*32; i += 256) {
        int r = i / 32, co = i % 32;
        float ll = 0.f, lh = 0.f, hl = 0.f, hh = 0.f;
        #pragma unroll
        for (int k = 0; k < 9; ++k) {
            ll += c_h0[k] * sLo[r][2*co + k];
            hl += c_h0[k] * sHi[r][2*co + k];
        }
        #pragma unroll
        for (int k = 0; k < 7; ++k) {
            lh += c_h1[k] * sLo[r][2*co + k + 1];
            hh += c_h1[k] * sHi[r][2*co + k + 1];
        }
        size_t idx = (size_t)z*16384 + (size_t)(hb + r)*128 + (wb + co);
        out[OFF_LL + idx] = ll;
        out[OFF_LH + idx] = lh;
        out[OFF_HL + idx] = hl;
        out[OFF_HH + idx] = hh;
    }
}

// ---------------------------------------------------------------------------
// Mask DWT: OR over reflected 9/7 windows
// ---------------------------------------------------------------------------
__global__ void maskdwt_kernel(float* __restrict__ out)
{
    int idx = blockIdx.x * 256 + threadIdx.x;
    if (idx >= BB*128*128) return;
    int b = idx >> 14, rem = idx & 16383;
    int ho = rem >> 7, wo = rem & 127;

    bool mll = false, mlh = false, mhl = false, mhh = false;
    #pragma unroll
    for (int dr = -4; dr <= 4; ++dr) {
        int gr = refl(2*ho + dr, HH);
        bool row9 = false, row7 = false;
        #pragma unroll
        for (int dc = -4; dc <= 4; ++dc) {
            int gc = refl(2*wo + dc, WW);
            bool v = g_ratio[(b*HH + gr)*WW + gc] > 0.f;
            row9 |= v;
            if (dc >= -3 && dc <= 3) row7 |= v;
        }
        mll |= row9;
        mlh |= row7;
        if (dr >= -3 && dr <= 3) { mhl |= row9; mhh |= row7; }
    }
    out[OFF_MLL + idx] = mll ? 1.f : 0.f;
    out[OFF_MLH + idx] = mlh ? 1.f : 0.f;
    out[OFF_MHL + idx] = mhl ? 1.f : 0.f;
    out[OFF_MHH + idx] = mhh ? 1.f : 0.f;
}

// ---------------------------------------------------------------------------
extern "C" void kernel_launch(void* const* d_in, const int* in_sizes, int n_in,
                              void* d_out, int out_size)
{
    const float* tensor = (const float*)d_in[0];
    const float* mask   = (const float*)d_in[1];
    const float* weight = (const float*)d_in[2];
    const float* bias   = (const float*)d_in[3];
    const float* u      = (const float*)d_in[4];
    const float* beta   = (const float*)d_in[5];
    const float* gamma  = (const float*)d_in[6];
    float* out = (float*)d_out;

    cudaFuncSetAttribute(conv_mma_kernel,
                         cudaFuncAttributeMaxDynamicSharedMemorySize, CV_SMEM);
    cudaFuncSetAttribute(gdn_mma_kernel,
                         cudaFuncAttributeMaxDynamicSharedMemorySize, GDN_SMEM);

    spectral_kernel<<<1, 256>>>(weight, u);                      // 0
    xprep_kernel<<<(BB*PH*PH*8 + 255)/256, 256>>>(tensor, mask); // 1
    wprep_kernel<<<(9*128*64 + 255)/256, 256>>>(weight);         // 2
    conv_mma_kernel<<<4096, 256, CV_SMEM>>>(bias, mask);         // 3 (profiled)
    gammaprep_kernel<<<(128*128 + 255)/256, 256>>>(gamma);       // 4
    gdn_mma_kernel<<<4096, 256, GDN_SMEM>>>(beta);               // 5
    dwt_kernel<<<dim3(4, 8, BB*CO), 256>>>(out);                 // 6
    maskdwt_kernel<<<(BB*128*128 + 255)/256, 256>>>(out);        // 7
}

// round 9
// speedup vs baseline: 3.6482x; 1.4422x over previous
#include <cuda_runtime.h>
#include <cuda_fp16.h>
#include <math.h>
#include <cstdint>

#define BB 8
#define CI 64
#define CO 128
#define HH 256
#define WW 256

#define SUB (BB*CO*128*128)
#define MSK (BB*128*128)
#define OFF_LL  0
#define OFF_MLL (SUB)
#define OFF_LH  (SUB + MSK)
#define OFF_HL  (2*SUB + MSK)
#define OFF_HH  (3*SUB + MSK)
#define OFF_MLH (4*SUB + MSK)
#define OFF_MHL (4*SUB + 2*MSK)
#define OFF_MHH (4*SUB + 3*MSK)

#define PH 258

// Scratch
__device__ float g_x[(size_t)BB*CO*HH*WW];    // final GDN output (DWT input)
__device__ float g_ratio[BB*HH*WW];
__device__ float g_inv_sigma;
__device__ uint4 g_xh4[(size_t)BB*PH*PH*8];   // padded NHWC fp16 hi (8 uint4 = 64ch)
__device__ uint4 g_xl4[(size_t)BB*PH*PH*8];   // lo
__device__ __half g_wh[9*128*64];             // [tap][oc][ch] fp16 (spectral-normalized)
__device__ __half g_gh[128*128];              // gamma [oc][ch] fp16

__constant__ float c_h0[9] = {
    0.026748757410810f, -0.016864118442875f, -0.078223266528990f,
    0.266864118442875f,  0.602949018236360f,  0.266864118442875f,
   -0.078223266528990f, -0.016864118442875f,  0.026748757410810f};
__constant__ float c_h1[7] = {
    0.091271763114250f, -0.057543526228500f, -0.591271763114250f,
    1.115087052457000f, -0.591271763114250f, -0.057543526228500f,
    0.091271763114250f};

__device__ __forceinline__ int refl(int i, int n) {
    return i < 0 ? -i : (i >= n ? 2*n - 2 - i : i);
}
__device__ __forceinline__ uint32_t smem_u32(const void* p) {
    uint32_t a;
    asm("{ .reg .u64 t; cvta.to.shared.u64 t, %1; cvt.u32.u64 %0, t; }" : "=r"(a) : "l"(p));
    return a;
}
__device__ __forceinline__ void cp16(uint32_t s, const void* g) {
    asm volatile("cp.async.cg.shared.global [%0], [%1], 16;" :: "r"(s), "l"(g));
}
__device__ __forceinline__ void cp_commit() {
    asm volatile("cp.async.commit_group;" ::: "memory");
}
__device__ __forceinline__ void cp_wait0() {
    asm volatile("cp.async.wait_group 0;" ::: "memory");
}
__device__ __forceinline__ void ldm_x4(uint32_t* r, uint32_t addr) {
    asm volatile("ldmatrix.sync.aligned.m8n8.x4.shared.b16 {%0,%1,%2,%3}, [%4];"
        : "=r"(r[0]), "=r"(r[1]), "=r"(r[2]), "=r"(r[3]) : "r"(addr));
}
__device__ __forceinline__ void mma_f16(float* c, const uint32_t* a, const uint32_t* b) {
    asm volatile(
        "mma.sync.aligned.m16n8k16.row.col.f32.f16.f16.f32 "
        "{%0,%1,%2,%3}, {%4,%5,%6,%7}, {%8,%9}, {%0,%1,%2,%3};"
        : "+f"(c[0]), "+f"(c[1]), "+f"(c[2]), "+f"(c[3])
        : "r"(a[0]), "r"(a[1]), "r"(a[2]), "r"(a[3]), "r"(b[0]), "r"(b[1]));
}
__device__ __forceinline__ uint32_t pkh(__half a, __half b) {
    return (uint32_t)__half_as_ushort(a) | ((uint32_t)__half_as_ushort(b) << 16);
}

// ---------------------------------------------------------------------------
// Spectral norm
// ---------------------------------------------------------------------------
__global__ void spectral_kernel(const float* __restrict__ w,
                                const float* __restrict__ u)
{
    __shared__ float sv[576];
    __shared__ float red[256];
    int tid = threadIdx.x;
    float p = 0.f;
    for (int j = tid; j < 576; j += 256) {
        float s = 0.f;
        #pragma unroll 4
        for (int o = 0; o < 128; ++o) s += w[o*576 + j] * u[o];
        sv[j] = s;
        p += s * s;
    }
    red[tid] = p; __syncthreads();
    for (int s = 128; s > 0; s >>= 1) {
        if (tid < s) red[tid] += red[tid + s];
        __syncthreads();
    }
    float vinv = 1.f / (sqrtf(red[0]) + 1e-12f);
    __syncthreads();
    float q = 0.f;
    if (tid < 128) {
        float s = 0.f;
        #pragma unroll 4
        for (int j = 0; j < 576; ++j) s += w[tid*576 + j] * sv[j];
        s *= vinv;
        q = s * s;
    }
    red[tid] = q; __syncthreads();
    for (int s = 128; s > 0; s >>= 1) {
        if (tid < s) red[tid] += red[tid + s];
        __syncthreads();
    }
    if (tid == 0) g_inv_sigma = rsqrtf(red[0]);
}

// ---------------------------------------------------------------------------
// xprep: padded NHWC fp16 hi/lo of x*mask
// ---------------------------------------------------------------------------
__global__ void xprep_kernel(const float* __restrict__ x,
                             const float* __restrict__ mask)
{
    int idx = blockIdx.x * 256 + threadIdx.x;
    if (idx >= BB*PH*PH*8) return;
    int j = idx & 7;
    int rem = idx >> 3;
    int pw = rem % PH; rem /= PH;
    int ph = rem % PH; int b = rem / PH;
    uint4 h4 = {0,0,0,0}, l4 = {0,0,0,0};
    if (ph > 0 && ph < PH-1 && pw > 0 && pw < PH-1) {
        int h = ph - 1, w = pw - 1;
        float m = mask[(b*HH + h)*WW + w];
        uint32_t hp[4], lp[4];
        #pragma unroll
        for (int k = 0; k < 4; ++k) {
            int c0 = j*8 + 2*k;
            float v0 = x[(((size_t)b*CI + c0)*HH + h)*WW + w] * m;
            float v1 = x[(((size_t)b*CI + c0 + 1)*HH + h)*WW + w] * m;
            __half h0 = __float2half_rn(v0), h1 = __float2half_rn(v1);
            __half e0 = __float2half_rn(v0 - __half2float(h0));
            __half e1 = __float2half_rn(v1 - __half2float(h1));
            hp[k] = pkh(h0, h1); lp[k] = pkh(e0, e1);
        }
        h4.x = hp[0]; h4.y = hp[1]; h4.z = hp[2]; h4.w = hp[3];
        l4.x = lp[0]; l4.y = lp[1]; l4.z = lp[2]; l4.w = lp[3];
    }
    g_xh4[idx] = h4;
    g_xl4[idx] = l4;
}

// ---------------------------------------------------------------------------
// wprep: [tap][oc][ch] fp16, spectral-normalized
// ---------------------------------------------------------------------------
__global__ void wprep_kernel(const float* __restrict__ weight)
{
    int idx = blockIdx.x * 256 + threadIdx.x;
    if (idx >= 9*128*64) return;
    int c = idx & 63, o = (idx >> 6) & 127, tap = idx >> 13;
    float wv = weight[(o*64 + c)*9 + tap] * g_inv_sigma;
    g_wh[(tap*128 + o)*64 + c] = __float2half_rn(wv);
}

// ---------------------------------------------------------------------------
// gammaprep: [oc][ch] fp16
// ---------------------------------------------------------------------------
__global__ void gammaprep_kernel(const float* __restrict__ gamma)
{
    int idx = blockIdx.x * 256 + threadIdx.x;
    if (idx >= 128*128) return;
    g_gh[idx] = __float2half_rn(gamma[idx]);
}

// ---------------------------------------------------------------------------
// Fused Conv3x3 (fp16 2-pass implicit GEMM) + partial-conv renorm + GDN
// CTA = 128 px (half row) x 128 oc.  One g_x write, no intermediate.
// smem layout (bytes):
//   [0, 99840)        conv A   (3 rows x 130 px x 256B)  -> later sD (128x129 f32)
//   [66048, 98816)                                       -> later xsq (128px x 256B)
//   [99840, 132608)   conv B double buffer (2 x 16KB)
//   [132608, 165376)  gamma (128 oc x 256B), prefetched at start
//   [165376, 165888)  sRat; [165888, 166400) sBias; [166400, 166912) sBeta
// ---------------------------------------------------------------------------
#define CV_SD    0
#define CV_XQ    66048
#define CV_B     99840
#define CV_G     132608
#define CV_RAT   165376
#define CV_BIAS  165888
#define CV_BETA  166400
#define CV_SMEM  166912

__global__ __launch_bounds__(256)
void convgdn_mma_kernel(const float* __restrict__ bias,
                        const float* __restrict__ beta,
                        const float* __restrict__ mask)
{
    extern __shared__ unsigned char dsm[];
    uint32_t sbase = smem_u32(dsm);
    uint32_t sA = sbase;
    uint32_t sB = sbase + CV_B;
    uint32_t sG = sbase + CV_G;
    uint32_t sXQ = sbase + CV_XQ;
    float* sD   = (float*)dsm;
    float* sRat  = (float*)(dsm + CV_RAT);
    float* sBias = (float*)(dsm + CV_BIAS);
    float* sBeta = (float*)(dsm + CV_BETA);

    int tid = threadIdx.x;
    int lane = tid & 31, wid = tid >> 5;
    int wm = (wid & 3) * 32;
    int wn = (wid >> 2) * 64;

    int t = blockIdx.x;
    int b = t >> 9, h = (t & 511) >> 1, q = t & 1;

    if (tid < 128) {
        sBias[tid] = bias[tid];
        sBeta[tid] = beta[tid];
    }

    // stage A: 3 rows x 130 px x 256B (hi chunks 0-7, lo chunks 8-15)
    for (int i = tid; i < 6240; i += 256) {
        int r = i / 2080, rem = i % 2080;
        int p = rem >> 4, c = rem & 15;
        size_t pix = ((size_t)(b*PH + h + r))*PH*8 + (size_t)(q*128 + p)*8;
        const uint4* src = (c < 8) ? (g_xh4 + pix + c) : (g_xl4 + pix + (c - 8));
        cp16(sA + (r*130 + p)*256 + ((c ^ (p & 7)) << 4), src);
    }
    // stage B tap 0 -> buf 0
    for (int i = tid; i < 1024; i += 256) {
        int o = i >> 3, c = i & 7;
        const __half* src = g_wh + (size_t)o*64 + c*8;
        cp16(sB + o*128 + ((c ^ (o & 7)) << 4), src);
    }
    // prefetch gamma
    for (int i = tid; i < 2048; i += 256) {
        int o = i >> 4, c = i & 15;
        const __half* src = g_gh + (size_t)o*128 + c*8;
        cp16(sG + o*256 + ((c ^ (o & 7)) << 4), src);
    }
    cp_commit();

    float acc[2][8][4];
    #pragma unroll
    for (int ma = 0; ma < 2; ++ma)
        #pragma unroll
        for (int nt = 0; nt < 8; ++nt)
            #pragma unroll
            for (int k = 0; k < 4; ++k) acc[ma][nt][k] = 0.f;

    for (int tap = 0; tap < 9; ++tap) {
        cp_wait0();
        __syncthreads();
        if (tap < 8) {
            int nt2 = tap + 1;
            uint32_t bu = (uint32_t)(nt2 & 1);
            for (int i = tid; i < 1024; i += 256) {
                int o = i >> 3, c = i & 7;
                const __half* src = g_wh + (size_t)(nt2*128 + o)*64 + c*8;
                cp16(sB + bu*16384 + o*128 + ((c ^ (o & 7)) << 4), src);
            }
            cp_commit();
        }
        int dh = tap / 3, dw = tap % 3;
        uint32_t abase = sA + (uint32_t)(dh*130)*256;
        uint32_t bbase = sB + (uint32_t)(tap & 1)*16384;
        #pragma unroll
        for (int ks = 0; ks < 4; ++ks) {
            // B fragments once (Wh chunks 0..7) — reused for hi and lo A halves
            uint32_t bf[8][2];
            #pragma unroll
            for (int nb = 0; nb < 4; ++nb) {
                int n = wn + nb*16 + (lane & 7) + ((lane >> 4) << 3);
                int ch = 2*ks + ((lane >> 3) & 1);
                uint32_t r4[4];
                ldm_x4(r4, bbase + n*128 + ((ch ^ (n & 7)) << 4));
                bf[2*nb][0] = r4[0]; bf[2*nb][1] = r4[1];
                bf[2*nb+1][0] = r4[2]; bf[2*nb+1][1] = r4[3];
            }
            #pragma unroll
            for (int half = 0; half < 2; ++half) {
                uint32_t a[2][4];
                #pragma unroll
                for (int ma = 0; ma < 2; ++ma) {
                    int m = wm + ma*16 + (lane & 7) + ((lane >> 3) & 1)*8;
                    int p = m + dw;
                    int ch = 2*ks + (lane >> 4) + half*8;
                    ldm_x4(a[ma], abase + p*256 + ((ch ^ (p & 7)) << 4));
                }
                #pragma unroll
                for (int ma = 0; ma < 2; ++ma)
                    #pragma unroll
                    for (int nt = 0; nt < 8; ++nt)
                        mma_f16(acc[ma][nt], a[ma], bf[nt]);
            }
        }
        __syncthreads();
    }

    // ---- partial-conv ratio ----
    int wq0 = q*128;
    if (tid < 128) {
        int wq = wq0 + tid;
        float s = 0.f;
        #pragma unroll
        for (int dh = -1; dh <= 1; ++dh) {
            int gh = h + dh;
            if ((unsigned)gh >= (unsigned)HH) continue;
            #pragma unroll
            for (int dw = -1; dw <= 1; ++dw) {
                int gw = wq + dw;
                if ((unsigned)gw >= (unsigned)WW) continue;
                s += mask[(b*HH + gh)*WW + gw];
            }
        }
        float ratio = s > 0.f ? 9.f / fmaxf(s, 1e-8f) : 0.f;
        sRat[tid] = ratio;
        g_ratio[(b*HH + h)*WW + wq] = ratio;
    }
    __syncthreads();

    // ---- conv fragments -> y in sD[oc][px] (ratio + bias fused) ----
    #pragma unroll
    for (int ma = 0; ma < 2; ++ma)
        #pragma unroll
        for (int nt = 0; nt < 8; ++nt) {
            int r = wm + ma*16 + (lane >> 2);
            int cb = wn + nt*8 + 2*(lane & 3);
            float rt0 = sRat[r], rt8 = sRat[r + 8];
            sD[cb*129 + r]           = rt0 > 0.f ? acc[ma][nt][0]*rt0 + sBias[cb]   : 0.f;
            sD[(cb + 1)*129 + r]     = rt0 > 0.f ? acc[ma][nt][1]*rt0 + sBias[cb+1] : 0.f;
            sD[cb*129 + r + 8]       = rt8 > 0.f ? acc[ma][nt][2]*rt8 + sBias[cb]   : 0.f;
            sD[(cb + 1)*129 + r + 8] = rt8 > 0.f ? acc[ma][nt][3]*rt8 + sBias[cb+1] : 0.f;
        }
    __syncthreads();

    // ---- xsq = fp16(y^2), [px][ch] rows of 256B ----
    for (int i = tid; i < 16384; i += 256) {
        int c = i & 127, p = i >> 7;
        float y = sD[c*129 + p];
        __half hv = __float2half_rn(y*y);
        uint32_t off = (uint32_t)p*256 + (uint32_t)(((c >> 3) ^ (p & 7)) << 4) + (c & 7)*2;
        *(__half*)(dsm + CV_XQ + off) = hv;
    }
    __syncthreads();

    // ---- GDN GEMM: D2[oc][px] = gamma[oc][ch] @ xsq[px][ch]^T (A=gamma, B=xsq) ----
    float ac2[2][8][4];
    #pragma unroll
    for (int ma = 0; ma < 2; ++ma)
        #pragma unroll
        for (int nt = 0; nt < 8; ++nt)
            #pragma unroll
            for (int k = 0; k < 4; ++k) ac2[ma][nt][k] = 0.f;

    #pragma unroll
    for (int ks = 0; ks < 8; ++ks) {
        uint32_t ag[2][4];
        #pragma unroll
        for (int ma = 0; ma < 2; ++ma) {
            int o = wm + ma*16 + (lane & 7) + ((lane >> 3) & 1)*8;
            int ch = 2*ks + (lane >> 4);
            ldm_x4(ag[ma], sG + o*256 + ((ch ^ (o & 7)) << 4));
        }
        uint32_t bx[8][2];
        #pragma unroll
        for (int nb = 0; nb < 4; ++nb) {
            int n = wn + nb*16 + (lane & 7) + ((lane >> 4) << 3);
            int ch = 2*ks + ((lane >> 3) & 1);
            uint32_t r4[4];
            ldm_x4(r4, sXQ + n*256 + ((ch ^ (n & 7)) << 4));
            bx[2*nb][0] = r4[0]; bx[2*nb][1] = r4[1];
            bx[2*nb+1][0] = r4[2]; bx[2*nb+1][1] = r4[3];
        }
        #pragma unroll
        for (int ma = 0; ma < 2; ++ma)
            #pragma unroll
            for (int nt = 0; nt < 8; ++nt)
                mma_f16(ac2[ma][nt], ag[ma], bx[nt]);
    }

    // ---- final: g_x = y * rsqrt(beta + D2), coalesced 32B-sector writes ----
    size_t gout = (size_t)b*CO*HH*WW + (size_t)h*WW + wq0;
    #pragma unroll
    for (int ma = 0; ma < 2; ++ma)
        #pragma unroll
        for (int nt = 0; nt < 8; ++nt) {
            int o = wm + ma*16 + (lane >> 2);
            int p = wn + nt*8 + 2*(lane & 3);
            float be0 = sBeta[o], be8 = sBeta[o + 8];
            float* g0 = g_x + gout + (size_t)o*(HH*WW) + p;
            float* g8 = g0 + (size_t)8*(HH*WW);
            g0[0] = sD[o*129 + p]       * rsqrtf(be0 + ac2[ma][nt][0]);
            g0[1] = sD[o*129 + p + 1]   * rsqrtf(be0 + ac2[ma][nt][1]);
            g8[0] = sD[(o+8)*129 + p]   * rsqrtf(be8 + ac2[ma][nt][2]);
            g8[1] = sD[(o+8)*129 + p+1] * rsqrtf(be8 + ac2[ma][nt][3]);
        }
}

// ---------------------------------------------------------------------------
// Fused 2D DWT (CDF 9/7 analysis)
// ---------------------------------------------------------------------------
__global__ __launch_bounds__(256)
void dwt_kernel(float* __restrict__ out)
{
    __shared__ float sT[40][72];
    __shared__ float sLo[16][72];
    __shared__ float sHi[16][72];

    int tid = threadIdx.x;
    int z = blockIdx.z;
    int hb = blockIdx.y * 16, wb = blockIdx.x * 32;
    const float* src = g_x + (size_t)z * HH * WW;

    for (int i = tid; i < 40*72; i += 256) {
        int r = i / 72, cc = i % 72;
        int gr = refl(2*hb - 4 + r, HH);
        int gc = refl(2*wb - 4 + cc, WW);
        sT[r][cc] = src[gr*WW + gc];
    }
    __syncthreads();

    for (int i = tid; i < 16*72; i += 256) {
        int r = i / 72, cc = i % 72;
        float lo = 0.f, hi = 0.f;
        #pragma unroll
        for (int k = 0; k < 9; ++k) lo += c_h0[k] * sT[2*r + k][cc];
        #pragma unroll
        for (int k = 0; k < 7; ++k) hi += c_h1[k] * sT[2*r + k + 1][cc];
        sLo[r][cc] = lo;
        sHi[r][cc] = hi;
    }
    __syncthreads();

    for (int i = tid; i < 16*32; i += 256) {
        int r = i / 32, co = i % 32;
        float ll = 0.f, lh = 0.f, hl = 0.f, hh = 0.f;
        #pragma unroll
        for (int k = 0; k < 9; ++k) {
            ll += c_h0[k] * sLo[r][2*co + k];
            hl += c_h0[k] * sHi[r][2*co + k];
        }
        #pragma unroll
        for (int k = 0; k < 7; ++k) {
            lh += c_h1[k] * sLo[r][2*co + k + 1];
            hh += c_h1[k] * sHi[r][2*co + k + 1];
        }
        size_t idx = (size_t)z*16384 + (size_t)(hb + r)*128 + (wb + co);
        out[OFF_LL + idx] = ll;
        out[OFF_LH + idx] = lh;
        out[OFF_HL + idx] = hl;
        out[OFF_HH + idx] = hh;
    }
}

// ---------------------------------------------------------------------------
// Mask DWT: OR over reflected 9/7 windows
// ---------------------------------------------------------------------------
__global__ void maskdwt_kernel(float* __restrict__ out)
{
    int idx = blockIdx.x * 256 + threadIdx.x;
    if (idx >= BB*128*128) return;
    int b = idx >> 14, rem = idx & 16383;
    int ho = rem >> 7, wo = rem & 127;

    bool mll = false, mlh = false, mhl = false, mhh = false;
    #pragma unroll
    for (int dr = -4; dr <= 4; ++dr) {
        int gr = refl(2*ho + dr, HH);
        bool row9 = false, row7 = false;
        #pragma unroll
        for (int dc = -4; dc <= 4; ++dc) {
            int gc = refl(2*wo + dc, WW);
            bool v = g_ratio[(b*HH + gr)*WW + gc] > 0.f;
            row9 |= v;
            if (dc >= -3 && dc <= 3) row7 |= v;
        }
        mll |= row9;
        mlh |= row7;
        if (dr >= -3 && dr <= 3) { mhl |= row9; mhh |= row7; }
    }
    out[OFF_MLL + idx] = mll ? 1.f : 0.f;
    out[OFF_MLH + idx] = mlh ? 1.f : 0.f;
    out[OFF_MHL + idx] = mhl ? 1.f : 0.f;
    out[OFF_MHH + idx] = mhh ? 1.f : 0.f;
}

// ---------------------------------------------------------------------------
extern "C" void kernel_launch(void* const* d_in, const int* in_sizes, int n_in,
                              void* d_out, int out_size)
{
    const float* tensor = (const float*)d_in[0];
    const float* mask   = (const float*)d_in[1];
    const float* weight = (const float*)d_in[2];
    const float* bias   = (const float*)d_in[3];
    const float* u      = (const float*)d_in[4];
    const float* beta   = (const float*)d_in[5];
    const float* gamma  = (const float*)d_in[6];
    float* out = (float*)d_out;

    cudaFuncSetAttribute(convgdn_mma_kernel,
                         cudaFuncAttributeMaxDynamicSharedMemorySize, CV_SMEM);

    spectral_kernel<<<1, 256>>>(weight, u);                        // 0
    xprep_kernel<<<(BB*PH*PH*8 + 255)/256, 256>>>(tensor, mask);   // 1
    wprep_kernel<<<(9*128*64 + 255)/256, 256>>>(weight);           // 2
    gammaprep_kernel<<<(128*128 + 255)/256, 256>>>(gamma);         // 3
    convgdn_mma_kernel<<<4096, 256, CV_SMEM>>>(bias, beta, mask);  // 4
    dwt_kernel<<<dim3(4, 8, BB*CO), 256>>>(out);                   // 5
    maskdwt_kernel<<<(BB*128*128 + 255)/256, 256>>>(out);          // 6
}

// round 10
// speedup vs baseline: 4.9452x; 1.3555x over previous
#include <cuda_runtime.h>
#include <cuda_fp16.h>
#include <math.h>
#include <cstdint>

#define BB 8
#define CI 64
#define CO 128
#define HH 256
#define WW 256

#define SUB (BB*CO*128*128)
#define MSK (BB*128*128)
#define OFF_LL  0
#define OFF_MLL (SUB)
#define OFF_LH  (SUB + MSK)
#define OFF_HL  (2*SUB + MSK)
#define OFF_HH  (3*SUB + MSK)
#define OFF_MLH (4*SUB + MSK)
#define OFF_MHL (4*SUB + 2*MSK)
#define OFF_MHH (4*SUB + 3*MSK)

#define PH 258

// Scratch
__device__ float g_x[(size_t)BB*CO*HH*WW];    // final GDN output (DWT input)
__device__ float g_ratio[BB*HH*WW];
__device__ float g_inv_sigma;
__device__ uint4 g_xh4[(size_t)BB*PH*PH*8];   // padded NHWC fp16 of x*mask (8 uint4 = 64ch)
__device__ __half g_wh[9*128*64];             // [tap][oc][ch] fp16 (spectral-normalized)
__device__ __half g_gh[128*128];              // gamma [oc][ch] fp16

__constant__ float c_h0[9] = {
    0.026748757410810f, -0.016864118442875f, -0.078223266528990f,
    0.266864118442875f,  0.602949018236360f,  0.266864118442875f,
   -0.078223266528990f, -0.016864118442875f,  0.026748757410810f};
__constant__ float c_h1[7] = {
    0.091271763114250f, -0.057543526228500f, -0.591271763114250f,
    1.115087052457000f, -0.591271763114250f, -0.057543526228500f,
    0.091271763114250f};

__device__ __forceinline__ int refl(int i, int n) {
    return i < 0 ? -i : (i >= n ? 2*n - 2 - i : i);
}
__device__ __forceinline__ uint32_t smem_u32(const void* p) {
    uint32_t a;
    asm("{ .reg .u64 t; cvta.to.shared.u64 t, %1; cvt.u32.u64 %0, t; }" : "=r"(a) : "l"(p));
    return a;
}
__device__ __forceinline__ void cp16(uint32_t s, const void* g) {
    asm volatile("cp.async.cg.shared.global [%0], [%1], 16;" :: "r"(s), "l"(g));
}
__device__ __forceinline__ void cp_commit() {
    asm volatile("cp.async.commit_group;" ::: "memory");
}
__device__ __forceinline__ void cp_wait0() {
    asm volatile("cp.async.wait_group 0;" ::: "memory");
}
__device__ __forceinline__ void ldm_x4(uint32_t* r, uint32_t addr) {
    asm volatile("ldmatrix.sync.aligned.m8n8.x4.shared.b16 {%0,%1,%2,%3}, [%4];"
        : "=r"(r[0]), "=r"(r[1]), "=r"(r[2]), "=r"(r[3]) : "r"(addr));
}
__device__ __forceinline__ void mma_f16(float* c, const uint32_t* a, const uint32_t* b) {
    asm volatile(
        "mma.sync.aligned.m16n8k16.row.col.f32.f16.f16.f32 "
        "{%0,%1,%2,%3}, {%4,%5,%6,%7}, {%8,%9}, {%0,%1,%2,%3};"
        : "+f"(c[0]), "+f"(c[1]), "+f"(c[2]), "+f"(c[3])
        : "r"(a[0]), "r"(a[1]), "r"(a[2]), "r"(a[3]), "r"(b[0]), "r"(b[1]));
}
__device__ __forceinline__ uint32_t pkh(__half a, __half b) {
    return (uint32_t)__half_as_ushort(a) | ((uint32_t)__half_as_ushort(b) << 16);
}

// ---------------------------------------------------------------------------
// Spectral norm
// ---------------------------------------------------------------------------
__global__ void spectral_kernel(const float* __restrict__ w,
                                const float* __restrict__ u)
{
    __shared__ float sv[576];
    __shared__ float red[256];
    int tid = threadIdx.x;
    float p = 0.f;
    for (int j = tid; j < 576; j += 256) {
        float s = 0.f;
        #pragma unroll 4
        for (int o = 0; o < 128; ++o) s += w[o*576 + j] * u[o];
        sv[j] = s;
        p += s * s;
    }
    red[tid] = p; __syncthreads();
    for (int s = 128; s > 0; s >>= 1) {
        if (tid < s) red[tid] += red[tid + s];
        __syncthreads();
    }
    float vinv = 1.f / (sqrtf(red[0]) + 1e-12f);
    __syncthreads();
    float q = 0.f;
    if (tid < 128) {
        float s = 0.f;
        #pragma unroll 4
        for (int j = 0; j < 576; ++j) s += w[tid*576 + j] * sv[j];
        s *= vinv;
        q = s * s;
    }
    red[tid] = q; __syncthreads();
    for (int s = 128; s > 0; s >>= 1) {
        if (tid < s) red[tid] += red[tid + s];
        __syncthreads();
    }
    if (tid == 0) g_inv_sigma = rsqrtf(red[0]);
}

// ---------------------------------------------------------------------------
// xprep: padded NHWC fp16 of x*mask (single split)
// ---------------------------------------------------------------------------
__global__ void xprep_kernel(const float* __restrict__ x,
                             const float* __restrict__ mask)
{
    int idx = blockIdx.x * 256 + threadIdx.x;
    if (idx >= BB*PH*PH*8) return;
    int j = idx & 7;
    int rem = idx >> 3;
    int pw = rem % PH; rem /= PH;
    int ph = rem % PH; int b = rem / PH;
    uint4 h4 = {0,0,0,0};
    if (ph > 0 && ph < PH-1 && pw > 0 && pw < PH-1) {
        int h = ph - 1, w = pw - 1;
        float m = mask[(b*HH + h)*WW + w];
        uint32_t hp[4];
        #pragma unroll
        for (int k = 0; k < 4; ++k) {
            int c0 = j*8 + 2*k;
            float v0 = x[(((size_t)b*CI + c0)*HH + h)*WW + w] * m;
            float v1 = x[(((size_t)b*CI + c0 + 1)*HH + h)*WW + w] * m;
            hp[k] = pkh(__float2half_rn(v0), __float2half_rn(v1));
        }
        h4.x = hp[0]; h4.y = hp[1]; h4.z = hp[2]; h4.w = hp[3];
    }
    g_xh4[idx] = h4;
}

// ---------------------------------------------------------------------------
// prep: weights [tap][oc][ch] fp16 (spectral-normalized) + gamma [oc][ch] fp16
// ---------------------------------------------------------------------------
__global__ void prep_kernel(const float* __restrict__ weight,
                            const float* __restrict__ gamma)
{
    int idx = blockIdx.x * 256 + threadIdx.x;
    if (idx < 9*128*64) {
        int c = idx & 63, o = (idx >> 6) & 127, tap = idx >> 13;
        float wv = weight[(o*64 + c)*9 + tap] * g_inv_sigma;
        g_wh[(tap*128 + o)*64 + c] = __float2half_rn(wv);
    } else if (idx < 9*128*64 + 128*128) {
        int gi = idx - 9*128*64;
        g_gh[gi] = __float2half_rn(gamma[gi]);
    }
}

// ---------------------------------------------------------------------------
// Fused Conv3x3 (single-pass fp16 implicit GEMM) + partial renorm + GDN
// CTA = 512 thr, tile 128 px x 128 oc, warp tile 32x32. y stays in registers:
// GDN GEMM oriented (A=xsq m=px, B=gamma n=oc) so its fragments match conv's.
// smem: [0,49920) A (3 rows x 130 px x 128B) -> later xsq (128 px x 256B)
//       [49920, 82688) B w-tap double buffer (2x16KB) -> later gamma (32KB)
//       [82688+] sRat, sBias, sBeta
// ---------------------------------------------------------------------------
#define CV_B     49920
#define CV_RAT   82688
#define CV_BIAS  83200
#define CV_BETA  83712
#define CV_SMEM  84224

__global__ __launch_bounds__(512, 1)
void convgdn_mma_kernel(const float* __restrict__ bias,
                        const float* __restrict__ beta,
                        const float* __restrict__ mask)
{
    extern __shared__ unsigned char dsm[];
    uint32_t sbase = smem_u32(dsm);
    uint32_t sA = sbase;                  // also xsq
    uint32_t sB = sbase + CV_B;           // also gamma
    float* sRat  = (float*)(dsm + CV_RAT);
    float* sBias = (float*)(dsm + CV_BIAS);
    float* sBeta = (float*)(dsm + CV_BETA);

    int tid = threadIdx.x;
    int lane = tid & 31, wid = tid >> 5;  // 16 warps
    int wm = (wid & 3) * 32;              // px offset
    int wn = (wid >> 2) * 32;             // oc offset

    int t = blockIdx.x;
    int b = t >> 9, h = (t & 511) >> 1, q = t & 1;

    if (tid < 128) {
        sBias[tid] = bias[tid];
        sBeta[tid] = beta[tid];
    }

    // stage A: 3 rows x 130 px x 128B
    for (int i = tid; i < 3120; i += 512) {
        int r = i / 1040, rem = i % 1040;
        int p = rem >> 3, c = rem & 7;
        const uint4* src = g_xh4
            + ((size_t)(b*PH + h + r))*PH*8 + (size_t)(q*128 + p)*8 + c;
        cp16(sA + (r*130 + p)*128 + ((c ^ (p & 7)) << 4), src);
    }
    // stage B tap 0 -> buf 0
    for (int i = tid; i < 1024; i += 512) {
        int o = i >> 3, c = i & 7;
        const __half* src = g_wh + (size_t)o*64 + c*8;
        cp16(sB + o*128 + ((c ^ (o & 7)) << 4), src);
    }
    cp_commit();

    float acc[2][4][4];
    #pragma unroll
    for (int ma = 0; ma < 2; ++ma)
        #pragma unroll
        for (int nt = 0; nt < 4; ++nt)
            #pragma unroll
            for (int k = 0; k < 4; ++k) acc[ma][nt][k] = 0.f;

    for (int tap = 0; tap < 9; ++tap) {
        cp_wait0();
        __syncthreads();
        if (tap < 8) {
            int nt2 = tap + 1;
            uint32_t bu = (uint32_t)(nt2 & 1);
            for (int i = tid; i < 1024; i += 512) {
                int o = i >> 3, c = i & 7;
                const __half* src = g_wh + (size_t)(nt2*128 + o)*64 + c*8;
                cp16(sB + bu*16384 + o*128 + ((c ^ (o & 7)) << 4), src);
            }
            cp_commit();
        }
        int dh = tap / 3, dw = tap % 3;
        uint32_t abase = sA + (uint32_t)(dh*130)*128;
        uint32_t bbase = sB + (uint32_t)(tap & 1)*16384;
        #pragma unroll
        for (int ks = 0; ks < 4; ++ks) {
            uint32_t bf[4][2];
            #pragma unroll
            for (int nb = 0; nb < 2; ++nb) {
                int n = wn + nb*16 + (lane & 7) + ((lane >> 4) << 3);
                int ch = 2*ks + ((lane >> 3) & 1);
                uint32_t r4[4];
                ldm_x4(r4, bbase + n*128 + ((ch ^ (n & 7)) << 4));
                bf[2*nb][0] = r4[0]; bf[2*nb][1] = r4[1];
                bf[2*nb+1][0] = r4[2]; bf[2*nb+1][1] = r4[3];
            }
            uint32_t a[2][4];
            #pragma unroll
            for (int ma = 0; ma < 2; ++ma) {
                int m = wm + ma*16 + (lane & 7) + ((lane >> 3) & 1)*8;
                int p = m + dw;
                int ch = 2*ks + (lane >> 4);
                ldm_x4(a[ma], abase + p*128 + ((ch ^ (p & 7)) << 4));
            }
            #pragma unroll
            for (int ma = 0; ma < 2; ++ma)
                #pragma unroll
                for (int nt = 0; nt < 4; ++nt)
                    mma_f16(acc[ma][nt], a[ma], bf[nt]);
        }
        __syncthreads();
    }

    // ---- load gamma into B region (B dead now) ----
    for (int i = tid; i < 2048; i += 512) {
        int o = i >> 4, c = i & 15;
        const __half* src = g_gh + (size_t)o*128 + c*8;
        cp16(sB + o*256 + ((c ^ (o & 7)) << 4), src);
    }
    cp_commit();

    // ---- partial-conv ratio ----
    int wq0 = q*128;
    if (tid < 128) {
        int wq = wq0 + tid;
        float s = 0.f;
        #pragma unroll
        for (int dh = -1; dh <= 1; ++dh) {
            int gh = h + dh;
            if ((unsigned)gh >= (unsigned)HH) continue;
            #pragma unroll
            for (int dw = -1; dw <= 1; ++dw) {
                int gw = wq + dw;
                if ((unsigned)gw >= (unsigned)WW) continue;
                s += mask[(b*HH + gh)*WW + gw];
            }
        }
        float ratio = s > 0.f ? 9.f / fmaxf(s, 1e-8f) : 0.f;
        sRat[tid] = ratio;
        g_ratio[(b*HH + h)*WW + wq] = ratio;
    }
    __syncthreads();

    // ---- y in regs (ratio+bias), xsq=fp16(y^2) into A region [px][ch 256B] ----
    #pragma unroll
    for (int ma = 0; ma < 2; ++ma)
        #pragma unroll
        for (int nt = 0; nt < 4; ++nt) {
            int r  = wm + ma*16 + (lane >> 2);
            int cb = wn + nt*8 + 2*(lane & 3);
            float rt0 = sRat[r], rt8 = sRat[r + 8];
            float y0 = rt0 > 0.f ? acc[ma][nt][0]*rt0 + sBias[cb]   : 0.f;
            float y1 = rt0 > 0.f ? acc[ma][nt][1]*rt0 + sBias[cb+1] : 0.f;
            float y2 = rt8 > 0.f ? acc[ma][nt][2]*rt8 + sBias[cb]   : 0.f;
            float y3 = rt8 > 0.f ? acc[ma][nt][3]*rt8 + sBias[cb+1] : 0.f;
            acc[ma][nt][0] = y0; acc[ma][nt][1] = y1;
            acc[ma][nt][2] = y2; acc[ma][nt][3] = y3;
            uint32_t c0 = (uint32_t)(cb >> 3), e0 = (uint32_t)(cb & 7);
            uint32_t c1 = (uint32_t)((cb+1) >> 3), e1 = (uint32_t)((cb+1) & 7);
            *(__half*)(dsm + (uint32_t)r*256 + ((c0 ^ (r & 7)) << 4) + e0*2)
                = __float2half_rn(y0*y0);
            *(__half*)(dsm + (uint32_t)r*256 + ((c1 ^ (r & 7)) << 4) + e1*2)
                = __float2half_rn(y1*y1);
            *(__half*)(dsm + (uint32_t)(r+8)*256 + ((c0 ^ ((r+8) & 7)) << 4) + e0*2)
                = __float2half_rn(y2*y2);
            *(__half*)(dsm + (uint32_t)(r+8)*256 + ((c1 ^ ((r+8) & 7)) << 4) + e1*2)
                = __float2half_rn(y3*y3);
        }
    cp_wait0();
    __syncthreads();

    // ---- GDN GEMM: D2[px][oc] = xsq[px][ch] @ gamma[oc][ch]^T ----
    float ac2[2][4][4];
    #pragma unroll
    for (int ma = 0; ma < 2; ++ma)
        #pragma unroll
        for (int nt = 0; nt < 4; ++nt)
            #pragma unroll
            for (int k = 0; k < 4; ++k) ac2[ma][nt][k] = 0.f;

    #pragma unroll
    for (int ks = 0; ks < 8; ++ks) {
        uint32_t a[2][4];
        #pragma unroll
        for (int ma = 0; ma < 2; ++ma) {
            int p = wm + ma*16 + (lane & 7) + ((lane >> 3) & 1)*8;
            int ch = 2*ks + (lane >> 4);
            ldm_x4(a[ma], sA + p*256 + ((ch ^ (p & 7)) << 4));
        }
        uint32_t bf[4][2];
        #pragma unroll
        for (int nb = 0; nb < 2; ++nb) {
            int n = wn + nb*16 + (lane & 7) + ((lane >> 4) << 3);
            int ch = 2*ks + ((lane >> 3) & 1);
            uint32_t r4[4];
            ldm_x4(r4, sB + n*256 + ((ch ^ (n & 7)) << 4));
            bf[2*nb][0] = r4[0]; bf[2*nb][1] = r4[1];
            bf[2*nb+1][0] = r4[2]; bf[2*nb+1][1] = r4[3];
        }
        #pragma unroll
        for (int ma = 0; ma < 2; ++ma)
            #pragma unroll
            for (int nt = 0; nt < 4; ++nt)
                mma_f16(ac2[ma][nt], a[ma], bf[nt]);
    }

    // ---- final: g_x[oc][px] = y * rsqrt(beta + D2), straight from regs ----
    size_t gout = (size_t)b*CO*HH*WW + (size_t)h*WW + wq0;
    #pragma unroll
    for (int ma = 0; ma < 2; ++ma)
        #pragma unroll
        for (int nt = 0; nt < 4; ++nt) {
            int r  = wm + ma*16 + (lane >> 2);
            int cb = wn + nt*8 + 2*(lane & 3);
            float be0 = sBeta[cb], be1 = sBeta[cb + 1];
            g_x[gout + (size_t)cb*(HH*WW) + r] =
                acc[ma][nt][0] * rsqrtf(be0 + ac2[ma][nt][0]);
            g_x[gout + (size_t)(cb+1)*(HH*WW) + r] =
                acc[ma][nt][1] * rsqrtf(be1 + ac2[ma][nt][1]);
            g_x[gout + (size_t)cb*(HH*WW) + r + 8] =
                acc[ma][nt][2] * rsqrtf(be0 + ac2[ma][nt][2]);
            g_x[gout + (size_t)(cb+1)*(HH*WW) + r + 8] =
                acc[ma][nt][3] * rsqrtf(be1 + ac2[ma][nt][3]);
        }
}

// ---------------------------------------------------------------------------
// Fused 2D DWT (CDF 9/7 analysis)
// ---------------------------------------------------------------------------
__global__ __launch_bounds__(256)
void dwt_kernel(float* __restrict__ out)
{
    __shared__ float sT[40][72];
    __shared__ float sLo[16][72];
    __shared__ float sHi[16][72];

    int tid = threadIdx.x;
    int z = blockIdx.z;
    int hb = blockIdx.y * 16, wb = blockIdx.x * 32;
    const float* src = g_x + (size_t)z * HH * WW;

    for (int i = tid; i < 40*72; i += 256) {
        int r = i / 72, cc = i % 72;
        int gr = refl(2*hb - 4 + r, HH);
        int gc = refl(2*wb - 4 + cc, WW);
        sT[r][cc] = src[gr*WW + gc];
    }
    __syncthreads();

    for (int i = tid; i < 16*72; i += 256) {
        int r = i / 72, cc = i % 72;
        float lo = 0.f, hi = 0.f;
        #pragma unroll
        for (int k = 0; k < 9; ++k) lo += c_h0[k] * sT[2*r + k][cc];
        #pragma unroll
        for (int k = 0; k < 7; ++k) hi += c_h1[k] * sT[2*r + k + 1][cc];
        sLo[r][cc] = lo;
        sHi[r][cc] = hi;
    }
    __syncthreads();

    for (int i = tid; i < 16*32; i += 256) {
        int r = i / 32, co = i % 32;
        float ll = 0.f, lh = 0.f, hl = 0.f, hh = 0.f;
        #pragma unroll
        for (int k = 0; k < 9; ++k) {
            ll += c_h0[k] * sLo[r][2*co + k];
            hl += c_h0[k] * sHi[r][2*co + k];
        }
        #pragma unroll
        for (int k = 0; k < 7; ++k) {
            lh += c_h1[k] * sLo[r][2*co + k + 1];
            hh += c_h1[k] * sHi[r][2*co + k + 1];
        }
        size_t idx = (size_t)z*16384 + (size_t)(hb + r)*128 + (wb + co);
        out[OFF_LL + idx] = ll;
        out[OFF_LH + idx] = lh;
        out[OFF_HL + idx] = hl;
        out[OFF_HH + idx] = hh;
    }
}

// ---------------------------------------------------------------------------
// Mask DWT: OR over reflected 9/7 windows
// ---------------------------------------------------------------------------
__global__ void maskdwt_kernel(float* __restrict__ out)
{
    int idx = blockIdx.x * 256 + threadIdx.x;
    if (idx >= BB*128*128) return;
    int b = idx >> 14, rem = idx & 16383;
    int ho = rem >> 7, wo = rem & 127;

    bool mll = false, mlh = false, mhl = false, mhh = false;
    #pragma unroll
    for (int dr = -4; dr <= 4; ++dr) {
        int gr = refl(2*ho + dr, HH);
        bool row9 = false, row7 = false;
        #pragma unroll
        for (int dc = -4; dc <= 4; ++dc) {
            int gc = refl(2*wo + dc, WW);
            bool v = g_ratio[(b*HH + gr)*WW + gc] > 0.f;
            row9 |= v;
            if (dc >= -3 && dc <= 3) row7 |= v;
        }
        mll |= row9;
        mlh |= row7;
        if (dr >= -3 && dr <= 3) { mhl |= row9; mhh |= row7; }
    }
    out[OFF_MLL + idx] = mll ? 1.f : 0.f;
    out[OFF_MLH + idx] = mlh ? 1.f : 0.f;
    out[OFF_MHL + idx] = mhl ? 1.f : 0.f;
    out[OFF_MHH + idx] = mhh ? 1.f : 0.f;
}

// ---------------------------------------------------------------------------
extern "C" void kernel_launch(void* const* d_in, const int* in_sizes, int n_in,
                              void* d_out, int out_size)
{
    const float* tensor = (const float*)d_in[0];
    const float* mask   = (const float*)d_in[1];
    const float* weight = (const float*)d_in[2];
    const float* bias   = (const float*)d_in[3];
    const float* u      = (const float*)d_in[4];
    const float* beta   = (const float*)d_in[5];
    const float* gamma  = (const float*)d_in[6];
    float* out = (float*)d_out;

    cudaFuncSetAttribute(convgdn_mma_kernel,
                         cudaFuncAttributeMaxDynamicSharedMemorySize, CV_SMEM);

    spectral_kernel<<<1, 256>>>(weight, u);                          // 0
    xprep_kernel<<<(BB*PH*PH*8 + 255)/256, 256>>>(tensor, mask);     // 1
    prep_kernel<<<(9*128*64 + 128*128 + 255)/256, 256>>>(weight, gamma); // 2
    convgdn_mma_kernel<<<4096, 512, CV_SMEM>>>(bias, beta, mask);    // 3 (profiled)
    dwt_kernel<<<dim3(4, 8, BB*CO), 256>>>(out);                     // 4
    maskdwt_kernel<<<(BB*128*128 + 255)/256, 256>>>(out);            // 5
}

// round 11
// speedup vs baseline: 5.3100x; 1.0738x over previous
#include <cuda_runtime.h>
#include <cuda_fp16.h>
#include <math.h>
#include <cstdint>

#define BB 8
#define CI 64
#define CO 128
#define HH 256
#define WW 256

#define SUB (BB*CO*128*128)
#define MSK (BB*128*128)
#define OFF_LL  0
#define OFF_MLL (SUB)
#define OFF_LH  (SUB + MSK)
#define OFF_HL  (2*SUB + MSK)
#define OFF_HH  (3*SUB + MSK)
#define OFF_MLH (4*SUB + MSK)
#define OFF_MHL (4*SUB + 2*MSK)
#define OFF_MHH (4*SUB + 3*MSK)

#define PH 258

// Scratch
__device__ float g_x[(size_t)BB*CO*HH*WW];    // final GDN output (DWT input)
__device__ float g_ratio[BB*HH*WW];
__device__ float g_inv_sigma;
// zero-initialized; xprep writes interior only, so borders stay zero forever
__device__ uint4 g_xh4[(size_t)BB*PH*PH*8];   // padded NHWC fp16 of x*mask
__device__ __half g_wh[9*128*64];             // [tap][oc][ch] fp16 (spectral-normalized)
__device__ __half g_gh[128*128];              // gamma [oc][ch] fp16

__constant__ float c_h0[9] = {
    0.026748757410810f, -0.016864118442875f, -0.078223266528990f,
    0.266864118442875f,  0.602949018236360f,  0.266864118442875f,
   -0.078223266528990f, -0.016864118442875f,  0.026748757410810f};
__constant__ float c_h1[7] = {
    0.091271763114250f, -0.057543526228500f, -0.591271763114250f,
    1.115087052457000f, -0.591271763114250f, -0.057543526228500f,
    0.091271763114250f};

__device__ __forceinline__ int refl(int i, int n) {
    return i < 0 ? -i : (i >= n ? 2*n - 2 - i : i);
}
__device__ __forceinline__ uint32_t smem_u32(const void* p) {
    uint32_t a;
    asm("{ .reg .u64 t; cvta.to.shared.u64 t, %1; cvt.u32.u64 %0, t; }" : "=r"(a) : "l"(p));
    return a;
}
__device__ __forceinline__ void cp16(uint32_t s, const void* g) {
    asm volatile("cp.async.cg.shared.global [%0], [%1], 16;" :: "r"(s), "l"(g));
}
__device__ __forceinline__ void cp_commit() {
    asm volatile("cp.async.commit_group;" ::: "memory");
}
__device__ __forceinline__ void cp_wait0() {
    asm volatile("cp.async.wait_group 0;" ::: "memory");
}
__device__ __forceinline__ void ldm_x4(uint32_t* r, uint32_t addr) {
    asm volatile("ldmatrix.sync.aligned.m8n8.x4.shared.b16 {%0,%1,%2,%3}, [%4];"
        : "=r"(r[0]), "=r"(r[1]), "=r"(r[2]), "=r"(r[3]) : "r"(addr));
}
__device__ __forceinline__ void mma_f16(float* c, const uint32_t* a, const uint32_t* b) {
    asm volatile(
        "mma.sync.aligned.m16n8k16.row.col.f32.f16.f16.f32 "
        "{%0,%1,%2,%3}, {%4,%5,%6,%7}, {%8,%9}, {%0,%1,%2,%3};"
        : "+f"(c[0]), "+f"(c[1]), "+f"(c[2]), "+f"(c[3])
        : "r"(a[0]), "r"(a[1]), "r"(a[2]), "r"(a[3]), "r"(b[0]), "r"(b[1]));
}
__device__ __forceinline__ uint32_t pkh(__half a, __half b) {
    return (uint32_t)__half_as_ushort(a) | ((uint32_t)__half_as_ushort(b) << 16);
}

// ---------------------------------------------------------------------------
// Spectral norm
// ---------------------------------------------------------------------------
__global__ void spectral_kernel(const float* __restrict__ w,
                                const float* __restrict__ u)
{
    __shared__ float sv[576];
    __shared__ float red[256];
    int tid = threadIdx.x;
    float p = 0.f;
    for (int j = tid; j < 576; j += 256) {
        float s = 0.f;
        #pragma unroll 4
        for (int o = 0; o < 128; ++o) s += w[o*576 + j] * u[o];
        sv[j] = s;
        p += s * s;
    }
    red[tid] = p; __syncthreads();
    for (int s = 128; s > 0; s >>= 1) {
        if (tid < s) red[tid] += red[tid + s];
        __syncthreads();
    }
    float vinv = 1.f / (sqrtf(red[0]) + 1e-12f);
    __syncthreads();
    float q = 0.f;
    if (tid < 128) {
        float s = 0.f;
        #pragma unroll 4
        for (int j = 0; j < 576; ++j) s += w[tid*576 + j] * sv[j];
        s *= vinv;
        q = s * s;
    }
    red[tid] = q; __syncthreads();
    for (int s = 128; s > 0; s >>= 1) {
        if (tid < s) red[tid] += red[tid + s];
        __syncthreads();
    }
    if (tid == 0) g_inv_sigma = rsqrtf(red[0]);
}

// ---------------------------------------------------------------------------
// xprep: coalesced reads (w across lanes) -> smem transpose -> contiguous
// uint4 writes.  CTA = (b, h, 32-w tile); 256 threads.
// ---------------------------------------------------------------------------
__global__ __launch_bounds__(256)
void xprep_kernel(const float* __restrict__ x,
                  const float* __restrict__ mask)
{
    __shared__ uint32_t sX[32*33];   // rows = channel pairs (64ch/2), col = w lane

    int tid = threadIdx.x;
    int lane = tid & 31, w_ = tid >> 5;      // 8 warps: 8 channels each
    int w0 = blockIdx.x * 32;
    int h  = blockIdx.y;
    int b  = blockIdx.z;

    float m = mask[(b*HH + h)*WW + w0 + lane];
    #pragma unroll
    for (int k = 0; k < 4; ++k) {
        int c0 = w_*8 + 2*k;
        float v0 = x[(((size_t)b*CI + c0)*HH + h)*WW + w0 + lane] * m;
        float v1 = x[(((size_t)b*CI + c0 + 1)*HH + h)*WW + w0 + lane] * m;
        sX[(w_*4 + k)*33 + lane] = pkh(__float2half_rn(v0), __float2half_rn(v1));
    }
    __syncthreads();

    int pwl = tid >> 3, j = tid & 7;
    uint4 v;
    v.x = sX[(j*4 + 0)*33 + pwl];
    v.y = sX[(j*4 + 1)*33 + pwl];
    v.z = sX[(j*4 + 2)*33 + pwl];
    v.w = sX[(j*4 + 3)*33 + pwl];
    g_xh4[((size_t)(b*PH + h + 1))*PH*8 + (size_t)(w0 + 1 + pwl)*8 + j] = v;
}

// ---------------------------------------------------------------------------
// prep: weights [tap][oc][ch] fp16 (spectral-normalized) + gamma [oc][ch] fp16
// ---------------------------------------------------------------------------
__global__ void prep_kernel(const float* __restrict__ weight,
                            const float* __restrict__ gamma)
{
    int idx = blockIdx.x * 256 + threadIdx.x;
    if (idx < 9*128*64) {
        int c = idx & 63, o = (idx >> 6) & 127, tap = idx >> 13;
        float wv = weight[(o*64 + c)*9 + tap] * g_inv_sigma;
        g_wh[(tap*128 + o)*64 + c] = __float2half_rn(wv);
    } else if (idx < 9*128*64 + 128*128) {
        int gi = idx - 9*128*64;
        g_gh[gi] = __float2half_rn(gamma[gi]);
    }
}

// ---------------------------------------------------------------------------
// Fused Conv3x3 (single-pass fp16 implicit GEMM) + partial renorm + GDN
// CTA = 256 thr, tile 64 px x 128 oc, warp tile 32x32, 2 CTAs/SM.
// smem: [0, 25344)  A (3 rows x 66 px x 128B) -> later xsq (64 px x 256B)
//       [25344, 58112) B w-tap double buffer (2x16KB) -> later gamma (32KB)
//       [58112+) sRat(64), sBias(128), sBeta(128)
// ---------------------------------------------------------------------------
#define CV_AROW  8448
#define CV_B     25344
#define CV_RAT   58112
#define CV_BIAS  58368
#define CV_BETA  58880
#define CV_SMEM  59392

__global__ __launch_bounds__(256, 2)
void convgdn_mma_kernel(const float* __restrict__ bias,
                        const float* __restrict__ beta,
                        const float* __restrict__ mask)
{
    extern __shared__ unsigned char dsm[];
    uint32_t sbase = smem_u32(dsm);
    uint32_t sA = sbase;                  // also xsq
    uint32_t sB = sbase + CV_B;           // also gamma
    float* sRat  = (float*)(dsm + CV_RAT);
    float* sBias = (float*)(dsm + CV_BIAS);
    float* sBeta = (float*)(dsm + CV_BETA);

    int tid = threadIdx.x;
    int lane = tid & 31, wid = tid >> 5;  // 8 warps
    int wm = (wid & 1) * 32;              // px offset (64/32)
    int wn = (wid >> 1) * 32;             // oc offset (128/32)

    int t = blockIdx.x;                   // 8192
    int b = t >> 10, rem = t & 1023;
    int h = rem >> 2, q = rem & 3;

    if (tid < 128) {
        sBias[tid] = bias[tid];
        sBeta[tid] = beta[tid];
    }

    // stage A: 3 rows x 66 px x 128B
    for (int i = tid; i < 1584; i += 256) {
        int r = i / 528, rem2 = i % 528;
        int p = rem2 >> 3, c = rem2 & 7;
        const uint4* src = g_xh4
            + ((size_t)(b*PH + h + r))*PH*8 + (size_t)(q*64 + p)*8 + c;
        cp16(sA + r*CV_AROW + p*128 + ((c ^ (p & 7)) << 4), src);
    }
    // stage B tap 0 -> buf 0
    for (int i = tid; i < 1024; i += 256) {
        int o = i >> 3, c = i & 7;
        const __half* src = g_wh + (size_t)o*64 + c*8;
        cp16(sB + o*128 + ((c ^ (o & 7)) << 4), src);
    }
    cp_commit();

    // partial-conv ratio (overlaps with staging latency)
    int wq0 = q*64;
    if (tid < 64) {
        int wq = wq0 + tid;
        float s = 0.f;
        #pragma unroll
        for (int dh = -1; dh <= 1; ++dh) {
            int gh = h + dh;
            if ((unsigned)gh >= (unsigned)HH) continue;
            #pragma unroll
            for (int dw = -1; dw <= 1; ++dw) {
                int gw = wq + dw;
                if ((unsigned)gw >= (unsigned)WW) continue;
                s += mask[(b*HH + gh)*WW + gw];
            }
        }
        float ratio = s > 0.f ? 9.f / fmaxf(s, 1e-8f) : 0.f;
        sRat[tid] = ratio;
        g_ratio[(b*HH + h)*WW + wq] = ratio;
    }

    float acc[2][4][4];
    #pragma unroll
    for (int ma = 0; ma < 2; ++ma)
        #pragma unroll
        for (int nt = 0; nt < 4; ++nt)
            #pragma unroll
            for (int k = 0; k < 4; ++k) acc[ma][nt][k] = 0.f;

    for (int tap = 0; tap < 9; ++tap) {
        cp_wait0();
        __syncthreads();
        if (tap < 8) {
            int nt2 = tap + 1;
            uint32_t bu = (uint32_t)(nt2 & 1);
            for (int i = tid; i < 1024; i += 256) {
                int o = i >> 3, c = i & 7;
                const __half* src = g_wh + (size_t)(nt2*128 + o)*64 + c*8;
                cp16(sB + bu*16384 + o*128 + ((c ^ (o & 7)) << 4), src);
            }
            cp_commit();
        }
        int dh = tap / 3, dw = tap % 3;
        uint32_t abase = sA + (uint32_t)dh*CV_AROW;
        uint32_t bbase = sB + (uint32_t)(tap & 1)*16384;
        #pragma unroll
        for (int ks = 0; ks < 4; ++ks) {
            uint32_t bf[4][2];
            #pragma unroll
            for (int nb = 0; nb < 2; ++nb) {
                int n = wn + nb*16 + (lane & 7) + ((lane >> 4) << 3);
                int ch = 2*ks + ((lane >> 3) & 1);
                uint32_t r4[4];
                ldm_x4(r4, bbase + n*128 + ((ch ^ (n & 7)) << 4));
                bf[2*nb][0] = r4[0]; bf[2*nb][1] = r4[1];
                bf[2*nb+1][0] = r4[2]; bf[2*nb+1][1] = r4[3];
            }
            uint32_t a[2][4];
            #pragma unroll
            for (int ma = 0; ma < 2; ++ma) {
                int m = wm + ma*16 + (lane & 7) + ((lane >> 3) & 1)*8;
                int p = m + dw;
                int ch = 2*ks + (lane >> 4);
                ldm_x4(a[ma], abase + p*128 + ((ch ^ (p & 7)) << 4));
            }
            #pragma unroll
            for (int ma = 0; ma < 2; ++ma)
                #pragma unroll
                for (int nt = 0; nt < 4; ++nt)
                    mma_f16(acc[ma][nt], a[ma], bf[nt]);
        }
        __syncthreads();
    }

    // ---- load gamma into B region (B dead now) ----
    for (int i = tid; i < 2048; i += 256) {
        int o = i >> 4, c = i & 15;
        const __half* src = g_gh + (size_t)o*128 + c*8;
        cp16(sB + o*256 + ((c ^ (o & 7)) << 4), src);
    }
    cp_commit();

    // ---- y in regs (ratio+bias), xsq=fp16(y^2) into A region [px][256B] ----
    #pragma unroll
    for (int ma = 0; ma < 2; ++ma)
        #pragma unroll
        for (int nt = 0; nt < 4; ++nt) {
            int r  = wm + ma*16 + (lane >> 2);
            int cb = wn + nt*8 + 2*(lane & 3);
            float rt0 = sRat[r], rt8 = sRat[r + 8];
            float y0 = rt0 > 0.f ? acc[ma][nt][0]*rt0 + sBias[cb]   : 0.f;
            float y1 = rt0 > 0.f ? acc[ma][nt][1]*rt0 + sBias[cb+1] : 0.f;
            float y2 = rt8 > 0.f ? acc[ma][nt][2]*rt8 + sBias[cb]   : 0.f;
            float y3 = rt8 > 0.f ? acc[ma][nt][3]*rt8 + sBias[cb+1] : 0.f;
            acc[ma][nt][0] = y0; acc[ma][nt][1] = y1;
            acc[ma][nt][2] = y2; acc[ma][nt][3] = y3;
            uint32_t c0 = (uint32_t)(cb >> 3), e0 = (uint32_t)(cb & 7);
            uint32_t c1 = (uint32_t)((cb+1) >> 3), e1 = (uint32_t)((cb+1) & 7);
            *(__half*)(dsm + (uint32_t)r*256 + ((c0 ^ (r & 7)) << 4) + e0*2)
                = __float2half_rn(y0*y0);
            *(__half*)(dsm + (uint32_t)r*256 + ((c1 ^ (r & 7)) << 4) + e1*2)
                = __float2half_rn(y1*y1);
            *(__half*)(dsm + (uint32_t)(r+8)*256 + ((c0 ^ ((r+8) & 7)) << 4) + e0*2)
                = __float2half_rn(y2*y2);
            *(__half*)(dsm + (uint32_t)(r+8)*256 + ((c1 ^ ((r+8) & 7)) << 4) + e1*2)
                = __float2half_rn(y3*y3);
        }
    cp_wait0();
    __syncthreads();

    // ---- GDN GEMM: D2[px][oc] = xsq[px][ch] @ gamma[oc][ch]^T ----
    float ac2[2][4][4];
    #pragma unroll
    for (int ma = 0; ma < 2; ++ma)
        #pragma unroll
        for (int nt = 0; nt < 4; ++nt)
            #pragma unroll
            for (int k = 0; k < 4; ++k) ac2[ma][nt][k] = 0.f;

    #pragma unroll
    for (int ks = 0; ks < 8; ++ks) {
        uint32_t a[2][4];
        #pragma unroll
        for (int ma = 0; ma < 2; ++ma) {
            int p = wm + ma*16 + (lane & 7) + ((lane >> 3) & 1)*8;
            int ch = 2*ks + (lane >> 4);
            ldm_x4(a[ma], sA + p*256 + ((ch ^ (p & 7)) << 4));
        }
        uint32_t bf[4][2];
        #pragma unroll
        for (int nb = 0; nb < 2; ++nb) {
            int n = wn + nb*16 + (lane & 7) + ((lane >> 4) << 3);
            int ch = 2*ks + ((lane >> 3) & 1);
            uint32_t r4[4];
            ldm_x4(r4, sB + n*256 + ((ch ^ (n & 7)) << 4));
            bf[2*nb][0] = r4[0]; bf[2*nb][1] = r4[1];
            bf[2*nb+1][0] = r4[2]; bf[2*nb+1][1] = r4[3];
        }
        #pragma unroll
        for (int ma = 0; ma < 2; ++ma)
            #pragma unroll
            for (int nt = 0; nt < 4; ++nt)
                mma_f16(ac2[ma][nt], a[ma], bf[nt]);
    }

    // ---- final: g_x[oc][px] = y * rsqrt(beta + D2), straight from regs ----
    size_t gout = (size_t)b*CO*HH*WW + (size_t)h*WW + wq0;
    #pragma unroll
    for (int ma = 0; ma < 2; ++ma)
        #pragma unroll
        for (int nt = 0; nt < 4; ++nt) {
            int r  = wm + ma*16 + (lane >> 2);
            int cb = wn + nt*8 + 2*(lane & 3);
            float be0 = sBeta[cb], be1 = sBeta[cb + 1];
            g_x[gout + (size_t)cb*(HH*WW) + r] =
                acc[ma][nt][0] * rsqrtf(be0 + ac2[ma][nt][0]);
            g_x[gout + (size_t)(cb+1)*(HH*WW) + r] =
                acc[ma][nt][1] * rsqrtf(be1 + ac2[ma][nt][1]);
            g_x[gout + (size_t)cb*(HH*WW) + r + 8] =
                acc[ma][nt][2] * rsqrtf(be0 + ac2[ma][nt][2]);
            g_x[gout + (size_t)(cb+1)*(HH*WW) + r + 8] =
                acc[ma][nt][3] * rsqrtf(be1 + ac2[ma][nt][3]);
        }
}

// ---------------------------------------------------------------------------
// Fused 2D DWT (CDF 9/7 analysis)
// ---------------------------------------------------------------------------
__global__ __launch_bounds__(256)
void dwt_kernel(float* __restrict__ out)
{
    __shared__ float sT[40][72];
    __shared__ float sLo[16][72];
    __shared__ float sHi[16][72];

    int tid = threadIdx.x;
    int z = blockIdx.z;
    int hb = blockIdx.y * 16, wb = blockIdx.x * 32;
    const float* src = g_x + (size_t)z * HH * WW;

    for (int i = tid; i < 40*72; i += 256) {
        int r = i / 72, cc = i % 72;
        int gr = refl(2*hb - 4 + r, HH);
        int gc = refl(2*wb - 4 + cc, WW);
        sT[r][cc] = src[gr*WW + gc];
    }
    __syncthreads();

    for (int i = tid; i < 16*72; i += 256) {
        int r = i / 72, cc = i % 72;
        float lo = 0.f, hi = 0.f;
        #pragma unroll
        for (int k = 0; k < 9; ++k) lo += c_h0[k] * sT[2*r + k][cc];
        #pragma unroll
        for (int k = 0; k < 7; ++k) hi += c_h1[k] * sT[2*r + k + 1][cc];
        sLo[r][cc] = lo;
        sHi[r][cc] = hi;
    }
    __syncthreads();

    for (int i = tid; i < 16*32; i += 256) {
        int r = i / 32, co = i % 32;
        float ll = 0.f, lh = 0.f, hl = 0.f, hh = 0.f;
        #pragma unroll
        for (int k = 0; k < 9; ++k) {
            ll += c_h0[k] * sLo[r][2*co + k];
            hl += c_h0[k] * sHi[r][2*co + k];
        }
        #pragma unroll
        for (int k = 0; k < 7; ++k) {
            lh += c_h1[k] * sLo[r][2*co + k + 1];
            hh += c_h1[k] * sHi[r][2*co + k + 1];
        }
        size_t idx = (size_t)z*16384 + (size_t)(hb + r)*128 + (wb + co);
        out[OFF_LL + idx] = ll;
        out[OFF_LH + idx] = lh;
        out[OFF_HL + idx] = hl;
        out[OFF_HH + idx] = hh;
    }
}

// ---------------------------------------------------------------------------
// Mask DWT: OR over reflected 9/7 windows
// ---------------------------------------------------------------------------
__global__ void maskdwt_kernel(float* __restrict__ out)
{
    int idx = blockIdx.x * 256 + threadIdx.x;
    if (idx >= BB*128*128) return;
    int b = idx >> 14, rem = idx & 16383;
    int ho = rem >> 7, wo = rem & 127;

    bool mll = false, mlh = false, mhl = false, mhh = false;
    #pragma unroll
    for (int dr = -4; dr <= 4; ++dr) {
        int gr = refl(2*ho + dr, HH);
        bool row9 = false, row7 = false;
        #pragma unroll
        for (int dc = -4; dc <= 4; ++dc) {
            int gc = refl(2*wo + dc, WW);
            bool v = g_ratio[(b*HH + gr)*WW + gc] > 0.f;
            row9 |= v;
            if (dc >= -3 && dc <= 3) row7 |= v;
        }
        mll |= row9;
        mlh |= row7;
        if (dr >= -3 && dr <= 3) { mhl |= row9; mhh |= row7; }
    }
    out[OFF_MLL + idx] = mll ? 1.f : 0.f;
    out[OFF_MLH + idx] = mlh ? 1.f : 0.f;
    out[OFF_MHL + idx] = mhl ? 1.f : 0.f;
    out[OFF_MHH + idx] = mhh ? 1.f : 0.f;
}

// ---------------------------------------------------------------------------
extern "C" void kernel_launch(void* const* d_in, const int* in_sizes, int n_in,
                              void* d_out, int out_size)
{
    const float* tensor = (const float*)d_in[0];
    const float* mask   = (const float*)d_in[1];
    const float* weight = (const float*)d_in[2];
    const float* bias   = (const float*)d_in[3];
    const float* u      = (const float*)d_in[4];
    const float* beta   = (const float*)d_in[5];
    const float* gamma  = (const float*)d_in[6];
    float* out = (float*)d_out;

    cudaFuncSetAttribute(convgdn_mma_kernel,
                         cudaFuncAttributeMaxDynamicSharedMemorySize, CV_SMEM);

    spectral_kernel<<<1, 256>>>(weight, u);                          // 0
    xprep_kernel<<<dim3(8, 256, 8), 256>>>(tensor, mask);            // 1
    prep_kernel<<<(9*128*64 + 128*128 + 255)/256, 256>>>(weight, gamma); // 2
    convgdn_mma_kernel<<<8192, 256, CV_SMEM>>>(bias, beta, mask);    // 3 (profiled)
    dwt_kernel<<<dim3(4, 8, BB*CO), 256>>>(out);                     // 4
    maskdwt_kernel<<<(BB*128*128 + 255)/256, 256>>>(out);            // 5
}